// round 5
// baseline (speedup 1.0000x reference)
#include <cuda_runtime.h>
#include <math.h>

#define NSEQ  4096
#define DIMM  1024
#define HEADS 16
#define HD    64
#define WIDTH 512
#define NW    8
#define NST   512
#define KEYW  1024

// ---------------- scratch ----------------
__device__ float g_xn[NSEQ*DIMM];
__device__ float g_qkv[NSEQ*3*DIMM];
__device__ float g_q2s[NSEQ*DIMM];
__device__ float g_state_qkv[NST*3*DIMM];
__device__ float g_st[NST*DIMM];
__device__ float g_qfs_raw[NST*DIMM];

__device__ float g_qn_main[HEADS*NSEQ*HD];
__device__ float g_kn_main[HEADS*NSEQ*HD];
__device__ float g_qn_ts[HEADS*NSEQ*HD];
__device__ float g_kn_ts[HEADS*NST*HD];
__device__ float g_qn_ss[HEADS*NST*HD];
__device__ float g_kn_ss[HEADS*NST*HD];
__device__ float g_qn_fs[HEADS*NST*HD];
__device__ float g_kn_fs[HEADS*NST*HD];

__device__ float g_attn_out[NSEQ*DIMM];
__device__ float g_ts_out[NSEQ*DIMM];
__device__ float g_state_cat[NST*2*DIMM];
__device__ float g_so[NST*DIMM];
__device__ float g_z[NST*DIMM];

// ---------------- layernorm ----------------
__global__ void __launch_bounds__(256) ln_kernel(const float* __restrict__ x,
        const float* __restrict__ gamma, const float* __restrict__ pos,
        float* __restrict__ out)
{
    int row = blockIdx.x;
    const float* xr = x + (long)row*DIMM;
    float* orow = out + (long)row*DIMM;
    __shared__ float red[256];
    float s = 0.f, s2 = 0.f;
    for (int i = threadIdx.x; i < DIMM; i += 256) { float v = xr[i]; s += v; s2 += v*v; }
    red[threadIdx.x] = s; __syncthreads();
    for (int o = 128; o; o >>= 1) { if (threadIdx.x < o) red[threadIdx.x] += red[threadIdx.x+o]; __syncthreads(); }
    float mu = red[0] * (1.f/DIMM);
    __syncthreads();
    red[threadIdx.x] = s2; __syncthreads();
    for (int o = 128; o; o >>= 1) { if (threadIdx.x < o) red[threadIdx.x] += red[threadIdx.x+o]; __syncthreads(); }
    float var = red[0] * (1.f/DIMM) - mu*mu;
    float inv = rsqrtf(var + 1e-5f);
    for (int i = threadIdx.x; i < DIMM; i += 256) {
        float v = (xr[i]-mu)*inv*gamma[i];
        if (pos) v += pos[(long)row*DIMM + i];
        orow[i] = v;
    }
}

// ---------------- TF32 helpers ----------------
__device__ __forceinline__ unsigned f2tf32(float f)
{
    unsigned r;
    asm("cvt.rna.tf32.f32 %0, %1;" : "=r"(r) : "f"(f));
    return r;
}

__device__ __forceinline__ void mma_tf32(float c[4], const unsigned a[4], const unsigned b[2])
{
    asm volatile(
        "mma.sync.aligned.m16n8k8.row.col.f32.tf32.tf32.f32 "
        "{%0,%1,%2,%3}, {%4,%5,%6,%7}, {%8,%9}, {%0,%1,%2,%3};"
        : "+f"(c[0]), "+f"(c[1]), "+f"(c[2]), "+f"(c[3])
        : "r"(a[0]), "r"(a[1]), "r"(a[2]), "r"(a[3]), "r"(b[0]), "r"(b[1]));
}

// ---------------- TF32 tensor-core GEMM ----------------
__global__ void __launch_bounds__(256) tgemm(const float* __restrict__ A,
        const float* __restrict__ B, float* __restrict__ C,
        int M, int N, int K, int accum)
{
    __shared__ unsigned As[2][16][132];
    __shared__ unsigned Bs[2][16][132];

    int tid = threadIdx.x;
    int warp = tid >> 5, lane = tid & 31;
    int wy = warp >> 1, wx = warp & 1;
    int g = lane >> 2, t4 = lane & 3;
    int m0 = blockIdx.y*128, n0 = blockIdx.x*128;

    int arow = tid >> 2;
    int acol = (tid & 3) * 4;
    int bkrow = tid >> 5;
    int bcol = lane * 4;

    const float* Abase = A + (long)(m0 + arow)*K + acol;
    const float* Bbase = B + (long)bkrow*N + n0 + bcol;

    float acc[2][8][4];
    #pragma unroll
    for (int mi = 0; mi < 2; mi++)
        #pragma unroll
        for (int nj = 0; nj < 8; nj++)
            #pragma unroll
            for (int c = 0; c < 4; c++) acc[mi][nj][c] = 0.f;

    float4 ra0, ra1, rb0, rb1;

    auto ldg = [&](int kt) {
        ra0 = *(const float4*)(Abase + kt*16);
        ra1 = *(const float4*)(Abase + kt*16 + (long)64*K);
        rb0 = *(const float4*)(Bbase + (long)kt*16*N);
        rb1 = *(const float4*)(Bbase + (long)(kt*16+8)*N);
    };
    auto sts = [&](int buf) {
        As[buf][acol+0][arow] = f2tf32(ra0.x);
        As[buf][acol+1][arow] = f2tf32(ra0.y);
        As[buf][acol+2][arow] = f2tf32(ra0.z);
        As[buf][acol+3][arow] = f2tf32(ra0.w);
        As[buf][acol+0][arow+64] = f2tf32(ra1.x);
        As[buf][acol+1][arow+64] = f2tf32(ra1.y);
        As[buf][acol+2][arow+64] = f2tf32(ra1.z);
        As[buf][acol+3][arow+64] = f2tf32(ra1.w);
        Bs[buf][bkrow][bcol+0] = f2tf32(rb0.x);
        Bs[buf][bkrow][bcol+1] = f2tf32(rb0.y);
        Bs[buf][bkrow][bcol+2] = f2tf32(rb0.z);
        Bs[buf][bkrow][bcol+3] = f2tf32(rb0.w);
        Bs[buf][bkrow+8][bcol+0] = f2tf32(rb1.x);
        Bs[buf][bkrow+8][bcol+1] = f2tf32(rb1.y);
        Bs[buf][bkrow+8][bcol+2] = f2tf32(rb1.z);
        Bs[buf][bkrow+8][bcol+3] = f2tf32(rb1.w);
    };

    ldg(0); sts(0);
    __syncthreads();

    int nkt = K >> 4;
    for (int kt = 0; kt < nkt; kt++) {
        int buf = kt & 1;
        if (kt + 1 < nkt) ldg(kt + 1);

        #pragma unroll
        for (int ks = 0; ks < 2; ks++) {
            int kk = ks*8;
            unsigned af[2][4], bf[8][2];
            #pragma unroll
            for (int mi = 0; mi < 2; mi++) {
                int mr = wy*32 + mi*16 + g;
                af[mi][0] = As[buf][kk + t4][mr];
                af[mi][1] = As[buf][kk + t4][mr + 8];
                af[mi][2] = As[buf][kk + t4 + 4][mr];
                af[mi][3] = As[buf][kk + t4 + 4][mr + 8];
            }
            #pragma unroll
            for (int nj = 0; nj < 8; nj++) {
                int nc = wx*64 + nj*8 + g;
                bf[nj][0] = Bs[buf][kk + t4][nc];
                bf[nj][1] = Bs[buf][kk + t4 + 4][nc];
            }
            #pragma unroll
            for (int mi = 0; mi < 2; mi++)
                #pragma unroll
                for (int nj = 0; nj < 8; nj++)
                    mma_tf32(acc[mi][nj], af[mi], bf[nj]);
        }

        if (kt + 1 < nkt) sts(buf ^ 1);
        __syncthreads();
    }

    #pragma unroll
    for (int mi = 0; mi < 2; mi++) {
        #pragma unroll
        for (int nj = 0; nj < 8; nj++) {
            int row = m0 + wy*32 + mi*16 + g;
            int col = n0 + wx*64 + nj*8 + t4*2;
            float* p0 = &C[(long)row*N + col];
            float* p1 = &C[(long)(row+8)*N + col];
            float2 v0 = make_float2(acc[mi][nj][0], acc[mi][nj][1]);
            float2 v1 = make_float2(acc[mi][nj][2], acc[mi][nj][3]);
            if (accum) {
                float2 o0 = *(float2*)p0, o1 = *(float2*)p1;
                v0.x += o0.x; v0.y += o0.y; v1.x += o1.x; v1.y += o1.y;
            }
            *(float2*)p0 = v0;
            *(float2*)p1 = v1;
        }
    }
}

// ---------------- l2norm + scale, head-major ----------------
__global__ void norm_heads(const float* __restrict__ src, int srcStride, int colOff,
        int rowOff, const float* __restrict__ scale, float* __restrict__ dst, int nrows)
{
    int row = blockIdx.x, h = blockIdx.y, d = threadIdx.x;
    float v = src[(long)(rowOff+row)*srcStride + colOff + h*HD + d];
    float s = v*v;
    #pragma unroll
    for (int o = 16; o; o >>= 1) s += __shfl_xor_sync(0xffffffffu, s, o);
    __shared__ float sh[2];
    if ((d & 31) == 0) sh[d>>5] = s;
    __syncthreads();
    float inv = 1.f / fmaxf(sqrtf(sh[0]+sh[1]), 1e-12f);
    dst[((long)h*nrows + row)*HD + d] = v*inv*scale[d];
}

// ---------------- flash attention: QK^T compensated tf32, PV single tf32 ----------------
#define FPAD 68
#define TILEU (64*FPAD)
#define FLASH_SMEM (6*TILEU*4 + 256*4)

__global__ void __launch_bounds__(256, 2) flashmma(
        const float* __restrict__ Q, int qHeadRows,
        const float* __restrict__ Kh, int kHeadRows,
        const float* __restrict__ Vall, long vstride, int vColHeadMul, int vColAdd,
        int vRowExtra,
        const float* __restrict__ bias,
        float* __restrict__ Out, long ostride, int oColMul, int oColAdd,
        int L, int nwin)
{
    extern __shared__ unsigned usm[];
    unsigned* QHI = usm;
    unsigned* QLO = usm + TILEU;
    unsigned* KHI = usm + 2*TILEU;
    unsigned* KLO = usm + 3*TILEU;
    unsigned* VS  = usm + 4*TILEU;
    unsigned* PT  = usm + 5*TILEU;
    float* SMAX = (float*)(usm + 6*TILEU);   // [64][2]
    float* SSUM = SMAX + 128;                // [64][2]

    int tid = threadIdx.x;
    int warp = tid >> 5, lane = tid & 31;
    int wy = warp >> 1, wx = warp & 1;
    int g = lane >> 2, t4 = lane & 3;

    int z = blockIdx.y;
    int h = z / nwin, w = z - h*nwin;
    int winw = qHeadRows / nwin;
    int i0 = blockIdx.x*64;
    int qrow0 = w*winw + i0;
    int kOff = (nwin > 1) ? (w-1)*winw : 0;

    const float* Qblk = Q + ((long)h*qHeadRows + qrow0)*64;
    const float* Kbase = Kh + (long)h*kHeadRows*64;
    const float* Vbase = Vall + vColHeadMul*h + vColAdd;
    const float* biasH = bias ? bias + (long)h*WIDTH*KEYW : nullptr;

    // load Q, split hi/lo, store [d][row]
    #pragma unroll
    for (int t = 0; t < 16; t++) {
        int e = tid + t*256;
        int r = e >> 6, c = e & 63;
        float v = Qblk[(long)r*64 + c];
        unsigned hi = f2tf32(v);
        QHI[c*FPAD + r] = hi;
        QLO[c*FPAD + r] = f2tf32(v - __uint_as_float(hi));
    }

    int mr = wy*16 + g;
    float m0r = -3.402823466e38f, m1r = -3.402823466e38f;
    float l0 = 0.f, l1 = 0.f;
    float acc[4][4];
    #pragma unroll
    for (int nj = 0; nj < 4; nj++)
        #pragma unroll
        for (int c = 0; c < 4; c++) acc[nj][c] = 0.f;

    int Lq = biasH ? (i0 + 576) : L;
    if (Lq > L) Lq = L;

    for (int c0 = 0; c0 < Lq; c0 += 64) {
        // load + split K [d][key]; V single [key][d]
        #pragma unroll
        for (int t = 0; t < 16; t++) {
            int e = tid + t*256;
            int r = e >> 6, cc = e & 63;
            int kr = kOff + c0 + r;
            float kv = (kr >= 0) ? Kbase[(long)kr*64 + cc] : 0.f;
            float vv = (kr >= 0) ? Vbase[(long)(kr + vRowExtra)*vstride + cc] : 0.f;
            unsigned khi = f2tf32(kv);
            KHI[cc*FPAD + r] = khi;
            KLO[cc*FPAD + r] = f2tf32(kv - __uint_as_float(khi));
            VS[r*FPAD + cc] = f2tf32(vv);
        }
        __syncthreads();

        // ---- S = Q @ K^T (compensated) ----
        float sf[4][4];
        #pragma unroll
        for (int nj = 0; nj < 4; nj++)
            #pragma unroll
            for (int c = 0; c < 4; c++) sf[nj][c] = 0.f;

        #pragma unroll
        for (int kk = 0; kk < 64; kk += 8) {
            unsigned ahi[4], alo[4];
            ahi[0] = QHI[(kk+t4)*FPAD + mr];
            ahi[1] = QHI[(kk+t4)*FPAD + mr + 8];
            ahi[2] = QHI[(kk+t4+4)*FPAD + mr];
            ahi[3] = QHI[(kk+t4+4)*FPAD + mr + 8];
            alo[0] = QLO[(kk+t4)*FPAD + mr];
            alo[1] = QLO[(kk+t4)*FPAD + mr + 8];
            alo[2] = QLO[(kk+t4+4)*FPAD + mr];
            alo[3] = QLO[(kk+t4+4)*FPAD + mr + 8];
            #pragma unroll
            for (int nj = 0; nj < 4; nj++) {
                int nc = wx*32 + nj*8 + g;
                unsigned bhi[2] = { KHI[(kk+t4)*FPAD + nc], KHI[(kk+t4+4)*FPAD + nc] };
                unsigned blo[2] = { KLO[(kk+t4)*FPAD + nc], KLO[(kk+t4+4)*FPAD + nc] };
                mma_tf32(sf[nj], ahi, bhi);
                mma_tf32(sf[nj], alo, bhi);
                mma_tf32(sf[nj], ahi, blo);
            }
        }

        // ---- scale + bias + mask ----
        int ir0 = i0 + mr, ir1 = ir0 + 8;
        #pragma unroll
        for (int nj = 0; nj < 4; nj++) {
            int j0 = c0 + wx*32 + nj*8 + 2*t4;
            #pragma unroll
            for (int c = 0; c < 4; c++) sf[nj][c] *= 8.f;
            if (biasH) {
                float2 b0 = *(const float2*)&biasH[(long)ir0*KEYW + j0];
                float2 b1 = *(const float2*)&biasH[(long)ir1*KEYW + j0];
                sf[nj][0] += b0.x; sf[nj][1] += b0.y;
                sf[nj][2] += b1.x; sf[nj][3] += b1.y;
                if (j0     > ir0 + 512) sf[nj][0] = -3.402823466e38f;
                if (j0 + 1 > ir0 + 512) sf[nj][1] = -3.402823466e38f;
                if (j0     > ir1 + 512) sf[nj][2] = -3.402823466e38f;
                if (j0 + 1 > ir1 + 512) sf[nj][3] = -3.402823466e38f;
            }
        }

        // ---- row max ----
        float pm0 = -3.402823466e38f, pm1 = -3.402823466e38f;
        #pragma unroll
        for (int nj = 0; nj < 4; nj++) {
            pm0 = fmaxf(pm0, fmaxf(sf[nj][0], sf[nj][1]));
            pm1 = fmaxf(pm1, fmaxf(sf[nj][2], sf[nj][3]));
        }
        pm0 = fmaxf(pm0, __shfl_xor_sync(0xffffffffu, pm0, 1));
        pm0 = fmaxf(pm0, __shfl_xor_sync(0xffffffffu, pm0, 2));
        pm1 = fmaxf(pm1, __shfl_xor_sync(0xffffffffu, pm1, 1));
        pm1 = fmaxf(pm1, __shfl_xor_sync(0xffffffffu, pm1, 2));
        if (t4 == 0) {
            SMAX[mr*2 + wx] = pm0;
            SMAX[(mr+8)*2 + wx] = pm1;
        }
        __syncthreads();
        float cmax0 = fmaxf(SMAX[mr*2], SMAX[mr*2+1]);
        float cmax1 = fmaxf(SMAX[(mr+8)*2], SMAX[(mr+8)*2+1]);

        float mn0 = fmaxf(m0r, cmax0);
        float mn1 = fmaxf(m1r, cmax1);
        float corr0 = __expf(m0r - mn0);
        float corr1 = __expf(m1r - mn1);
        m0r = mn0; m1r = mn1;

        // exp + partial sums + write P transposed [key][row] (single tf32)
        float ps0 = 0.f, ps1 = 0.f;
        #pragma unroll
        for (int nj = 0; nj < 4; nj++) {
            int j0 = wx*32 + nj*8 + 2*t4;
            float p00 = __expf(sf[nj][0] - mn0);
            float p01 = __expf(sf[nj][1] - mn0);
            float p10 = __expf(sf[nj][2] - mn1);
            float p11 = __expf(sf[nj][3] - mn1);
            ps0 += p00 + p01;
            ps1 += p10 + p11;
            PT[j0*FPAD + mr]       = f2tf32(p00);
            PT[(j0+1)*FPAD + mr]   = f2tf32(p01);
            PT[j0*FPAD + mr+8]     = f2tf32(p10);
            PT[(j0+1)*FPAD + mr+8] = f2tf32(p11);
        }
        ps0 += __shfl_xor_sync(0xffffffffu, ps0, 1);
        ps0 += __shfl_xor_sync(0xffffffffu, ps0, 2);
        ps1 += __shfl_xor_sync(0xffffffffu, ps1, 1);
        ps1 += __shfl_xor_sync(0xffffffffu, ps1, 2);
        if (t4 == 0) {
            SSUM[mr*2 + wx] = ps0;
            SSUM[(mr+8)*2 + wx] = ps1;
        }

        // rescale accumulators
        #pragma unroll
        for (int nj = 0; nj < 4; nj++) {
            acc[nj][0] *= corr0; acc[nj][1] *= corr0;
            acc[nj][2] *= corr1; acc[nj][3] *= corr1;
        }
        __syncthreads();

        l0 = l0*corr0 + SSUM[mr*2] + SSUM[mr*2+1];
        l1 = l1*corr1 + SSUM[(mr+8)*2] + SSUM[(mr+8)*2+1];

        // ---- acc += P @ V (single tf32) ----
        #pragma unroll
        for (int kk = 0; kk < 64; kk += 8) {
            unsigned ap[4];
            ap[0] = PT[(kk+t4)*FPAD + mr];
            ap[1] = PT[(kk+t4)*FPAD + mr + 8];
            ap[2] = PT[(kk+t4+4)*FPAD + mr];
            ap[3] = PT[(kk+t4+4)*FPAD + mr + 8];
            #pragma unroll
            for (int nj = 0; nj < 4; nj++) {
                int nc = wx*32 + nj*8 + g;
                unsigned bv[2] = { VS[(kk+t4)*FPAD + nc], VS[(kk+t4+4)*FPAD + nc] };
                mma_tf32(acc[nj], ap, bv);
            }
        }
        __syncthreads();
    }

    // epilogue
    float inv0 = 1.f / l0, inv1 = 1.f / l1;
    #pragma unroll
    for (int nj = 0; nj < 4; nj++) {
        int col = h*oColMul + oColAdd + wx*32 + nj*8 + 2*t4;
        long r0 = (long)(qrow0 + mr)*ostride + col;
        long r1 = (long)(qrow0 + mr + 8)*ostride + col;
        *(float2*)&Out[r0] = make_float2(acc[nj][0]*inv0, acc[nj][1]*inv0);
        *(float2*)&Out[r1] = make_float2(acc[nj][2]*inv1, acc[nj][3]*inv1);
    }
}

// ---------------- memories copy ----------------
__global__ void memories_kernel(const float* __restrict__ qkv, float* __restrict__ out)
{
    int idx = blockIdx.x*256 + threadIdx.x;
    if (idx >= 2*HEADS*WIDTH*HD) return;
    int d = idx & 63;
    int i = (idx >> 6) & 511;
    int h = (idx >> 15) & 15;
    int s = idx >> 19;
    out[idx] = qkv[(long)(3584+i)*3072 + (s ? 2048 : 1024) + h*HD + d];
}

// ---------------- new_states ----------------
__global__ void newstates_kernel(const float* __restrict__ gz, const float* __restrict__ bg,
        const float* __restrict__ beta, const float* __restrict__ init_state,
        float* __restrict__ out)
{
    int idx = blockIdx.x*256 + threadIdx.x;
    if (idx >= NST*DIMM) return;
    int c = idx & (DIMM-1);
    float sig = 1.f/(1.f+expf(-beta[c]));
    float z = gz[idx] + bg[c];
    out[idx] = sig*z + (1.f-sig)*init_state[idx];
}

// ---------------- host launch ----------------
static float* symaddr(const void* s)
{
    void* p = nullptr;
    cudaGetSymbolAddress(&p, s);
    return (float*)p;
}

extern "C" void kernel_launch(void* const* d_in, const int* in_sizes, int n_in,
                              void* d_out, int out_size)
{
    const float* x       = (const float*)d_in[0];
    const float* bias    = (const float*)d_in[1];
    const float* gamma   = (const float*)d_in[2];
    const float* w_qkv   = (const float*)d_in[3];
    const float* q_scale = (const float*)d_in[4];
    const float* k_scale = (const float*)d_in[5];
    const float* w_out   = (const float*)d_in[6];
    const float* s_gamma = (const float*)d_in[7];
    const float* w_q2s   = (const float*)d_in[8];
    const float* w_qfs   = (const float*)d_in[9];
    const float* w_sqkv  = (const float*)d_in[10];
    const float* init_st = (const float*)d_in[11];
    const float* pos_ids = (const float*)d_in[12];
    const float* w_sout  = (const float*)d_in[13];
    const float* ts_q    = (const float*)d_in[14];
    const float* ts_k    = (const float*)d_in[15];
    const float* ss_q    = (const float*)d_in[16];
    const float* ss_k    = (const float*)d_in[17];
    const float* fs_q    = (const float*)d_in[18];
    const float* fs_k    = (const float*)d_in[19];
    const float* w_gate  = (const float*)d_in[20];
    const float* b_gate  = (const float*)d_in[21];
    const float* beta    = (const float*)d_in[22];
    float* out = (float*)d_out;

    float* xn   = symaddr(g_xn);
    float* qkv  = symaddr(g_qkv);
    float* q2s  = symaddr(g_q2s);
    float* sqkv = symaddr(g_state_qkv);
    float* st   = symaddr(g_st);
    float* qfsr = symaddr(g_qfs_raw);
    float* qnm  = symaddr(g_qn_main);
    float* knm  = symaddr(g_kn_main);
    float* qnts = symaddr(g_qn_ts);
    float* knts = symaddr(g_kn_ts);
    float* qnss = symaddr(g_qn_ss);
    float* knss = symaddr(g_kn_ss);
    float* qnfs = symaddr(g_qn_fs);
    float* knfs = symaddr(g_kn_fs);
    float* aout = symaddr(g_attn_out);
    float* tout = symaddr(g_ts_out);
    float* scat = symaddr(g_state_cat);
    float* so   = symaddr(g_so);
    float* zb   = symaddr(g_z);

    cudaFuncSetAttribute(flashmma, cudaFuncAttributeMaxDynamicSharedMemorySize, FLASH_SMEM);

    // 1) layernorms
    ln_kernel<<<NSEQ, 256>>>(x, gamma, nullptr, xn);
    ln_kernel<<<NST, 256>>>(init_st, s_gamma, pos_ids, st);

    // 2) projections (TF32 tensor cores)
    tgemm<<<dim3(3072/128, NSEQ/128), 256>>>(xn, w_qkv, qkv, NSEQ, 3072, DIMM, 0);
    tgemm<<<dim3(DIMM/128, NSEQ/128), 256>>>(xn, w_q2s, q2s, NSEQ, DIMM, DIMM, 0);
    tgemm<<<dim3(3072/128, NST/128), 256>>>(init_st, w_sqkv, sqkv, NST, 3072, DIMM, 0);
    tgemm<<<dim3(DIMM/128, NST/128), 256>>>(st, w_qfs, qfsr, NST, DIMM, DIMM, 0);

    // 3) l2norm + scale, head-major
    norm_heads<<<dim3(NSEQ, HEADS), 64>>>(qkv, 3072, 0,    0,    q_scale, qnm,  NSEQ);
    norm_heads<<<dim3(NSEQ, HEADS), 64>>>(qkv, 3072, 1024, 0,    k_scale, knm,  NSEQ);
    norm_heads<<<dim3(NSEQ, HEADS), 64>>>(q2s, 1024, 0,    0,    ts_q,    qnts, NSEQ);
    norm_heads<<<dim3(NST,  HEADS), 64>>>(sqkv, 3072, 1024, 0,   ts_k,    knts, NST);
    norm_heads<<<dim3(NST,  HEADS), 64>>>(sqkv, 3072, 0,    0,   ss_q,    qnss, NST);
    norm_heads<<<dim3(NST,  HEADS), 64>>>(sqkv, 3072, 1024, 0,   ss_k,    knss, NST);
    norm_heads<<<dim3(NST,  HEADS), 64>>>(qfsr, 1024, 0,    0,   fs_q,    qnfs, NST);
    norm_heads<<<dim3(NST,  HEADS), 64>>>(qkv,  3072, 1024, 3584, fs_k,   knfs, NST);

    // 4) fused attentions
    flashmma<<<dim3(WIDTH/64, HEADS*NW), 256, FLASH_SMEM>>>(
        qnm, NSEQ, knm, NSEQ, qkv, 3072, HD, 2048, 0, bias,
        aout, DIMM, HD, 0, KEYW, NW);
    flashmma<<<dim3(NSEQ/64, HEADS), 256, FLASH_SMEM>>>(
        qnts, NSEQ, knts, NST, sqkv, 3072, HD, 2048, 0, nullptr,
        tout, DIMM, HD, 0, NST, 1);
    flashmma<<<dim3(NST/64, HEADS), 256, FLASH_SMEM>>>(
        qnss, NST, knss, NST, sqkv, 3072, HD, 2048, 0, nullptr,
        scat, 2*DIMM, 2*HD, 0, NST, 1);
    flashmma<<<dim3(NST/64, HEADS), 256, FLASH_SMEM>>>(
        qnfs, NST, knfs, NST, qkv, 3072, HD, 2048, 3584, nullptr,
        scat, 2*DIMM, 2*HD, HD, NST, 1);

    // 5) output projections
    tgemm<<<dim3(DIMM/128, NSEQ/128), 256>>>(aout, w_out, out, NSEQ, DIMM, DIMM, 0);
    tgemm<<<dim3(DIMM/128, NSEQ/128), 256>>>(tout, w_out + (long)DIMM*DIMM, out, NSEQ, DIMM, DIMM, 1);

    // 6) memories
    memories_kernel<<<(2*HEADS*WIDTH*HD)/256, 256>>>(qkv, out + (long)NSEQ*DIMM);

    // 7) state output path
    tgemm<<<dim3(DIMM/128, NST/128), 256>>>(scat, w_sout, so, NST, DIMM, 2*DIMM, 0);
    tgemm<<<dim3(DIMM/128, NST/128), 256>>>(so, w_gate, zb, NST, DIMM, DIMM, 0);
    newstates_kernel<<<(NST*DIMM)/256, 256>>>(zb, b_gate, beta, init_st,
            out + (long)NSEQ*DIMM + 2*HEADS*WIDTH*HD);
}

// round 6
// speedup vs baseline: 1.1687x; 1.1687x over previous
#include <cuda_runtime.h>
#include <math.h>

#define NSEQ  4096
#define DIMM  1024
#define HEADS 16
#define HD    64
#define WIDTH 512
#define NW    8
#define NST   512
#define KEYW  1024

// ---------------- scratch ----------------
__device__ float g_xn[NSEQ*DIMM];
__device__ float g_qkv[NSEQ*3*DIMM];
__device__ float g_q2s[NSEQ*DIMM];
__device__ float g_state_qkv[NST*3*DIMM];
__device__ float g_st[NST*DIMM];
__device__ float g_qfs_raw[NST*DIMM];

__device__ float g_qn_main[HEADS*NSEQ*HD];
__device__ float g_kn_main[HEADS*NSEQ*HD];
__device__ float g_qn_ts[HEADS*NSEQ*HD];
__device__ float g_kn_ts[HEADS*NST*HD];
__device__ float g_qn_ss[HEADS*NST*HD];
__device__ float g_kn_ss[HEADS*NST*HD];
__device__ float g_qn_fs[HEADS*NST*HD];
__device__ float g_kn_fs[HEADS*NST*HD];

__device__ float g_attn_out[NSEQ*DIMM];
__device__ float g_ts_out[NSEQ*DIMM];
__device__ float g_state_cat[NST*2*DIMM];
__device__ float g_so[NST*DIMM];
__device__ float g_z[NST*DIMM];

// ---------------- layernorm ----------------
__global__ void __launch_bounds__(256) ln_kernel(const float* __restrict__ x,
        const float* __restrict__ gamma, const float* __restrict__ pos,
        float* __restrict__ out)
{
    int row = blockIdx.x;
    const float* xr = x + (long)row*DIMM;
    float* orow = out + (long)row*DIMM;
    __shared__ float red[256];
    float s = 0.f, s2 = 0.f;
    for (int i = threadIdx.x; i < DIMM; i += 256) { float v = xr[i]; s += v; s2 += v*v; }
    red[threadIdx.x] = s; __syncthreads();
    for (int o = 128; o; o >>= 1) { if (threadIdx.x < o) red[threadIdx.x] += red[threadIdx.x+o]; __syncthreads(); }
    float mu = red[0] * (1.f/DIMM);
    __syncthreads();
    red[threadIdx.x] = s2; __syncthreads();
    for (int o = 128; o; o >>= 1) { if (threadIdx.x < o) red[threadIdx.x] += red[threadIdx.x+o]; __syncthreads(); }
    float var = red[0] * (1.f/DIMM) - mu*mu;
    float inv = rsqrtf(var + 1e-5f);
    for (int i = threadIdx.x; i < DIMM; i += 256) {
        float v = (xr[i]-mu)*inv*gamma[i];
        if (pos) v += pos[(long)row*DIMM + i];
        orow[i] = v;
    }
}

// ---------------- TF32 helpers ----------------
__device__ __forceinline__ unsigned f2tf32(float f)
{
    unsigned r;
    asm("cvt.rna.tf32.f32 %0, %1;" : "=r"(r) : "f"(f));
    return r;
}

__device__ __forceinline__ void mma_tf32(float c[4], const unsigned a[4], const unsigned b[2])
{
    asm volatile(
        "mma.sync.aligned.m16n8k8.row.col.f32.tf32.tf32.f32 "
        "{%0,%1,%2,%3}, {%4,%5,%6,%7}, {%8,%9}, {%0,%1,%2,%3};"
        : "+f"(c[0]), "+f"(c[1]), "+f"(c[2]), "+f"(c[3])
        : "r"(a[0]), "r"(a[1]), "r"(a[2]), "r"(a[3]), "r"(b[0]), "r"(b[1]));
}

// ---------------- TF32 tensor-core GEMM ----------------
__global__ void __launch_bounds__(256) tgemm(const float* __restrict__ A,
        const float* __restrict__ B, float* __restrict__ C,
        int M, int N, int K, int accum)
{
    __shared__ unsigned As[2][16][132];
    __shared__ unsigned Bs[2][16][132];

    int tid = threadIdx.x;
    int warp = tid >> 5, lane = tid & 31;
    int wy = warp >> 1, wx = warp & 1;
    int g = lane >> 2, t4 = lane & 3;
    int m0 = blockIdx.y*128, n0 = blockIdx.x*128;

    int arow = tid >> 2;
    int acol = (tid & 3) * 4;
    int bkrow = tid >> 5;
    int bcol = lane * 4;

    const float* Abase = A + (long)(m0 + arow)*K + acol;
    const float* Bbase = B + (long)bkrow*N + n0 + bcol;

    float acc[2][8][4];
    #pragma unroll
    for (int mi = 0; mi < 2; mi++)
        #pragma unroll
        for (int nj = 0; nj < 8; nj++)
            #pragma unroll
            for (int c = 0; c < 4; c++) acc[mi][nj][c] = 0.f;

    float4 ra0, ra1, rb0, rb1;

    auto ldg = [&](int kt) {
        ra0 = *(const float4*)(Abase + kt*16);
        ra1 = *(const float4*)(Abase + kt*16 + (long)64*K);
        rb0 = *(const float4*)(Bbase + (long)kt*16*N);
        rb1 = *(const float4*)(Bbase + (long)(kt*16+8)*N);
    };
    auto sts = [&](int buf) {
        As[buf][acol+0][arow] = f2tf32(ra0.x);
        As[buf][acol+1][arow] = f2tf32(ra0.y);
        As[buf][acol+2][arow] = f2tf32(ra0.z);
        As[buf][acol+3][arow] = f2tf32(ra0.w);
        As[buf][acol+0][arow+64] = f2tf32(ra1.x);
        As[buf][acol+1][arow+64] = f2tf32(ra1.y);
        As[buf][acol+2][arow+64] = f2tf32(ra1.z);
        As[buf][acol+3][arow+64] = f2tf32(ra1.w);
        Bs[buf][bkrow][bcol+0] = f2tf32(rb0.x);
        Bs[buf][bkrow][bcol+1] = f2tf32(rb0.y);
        Bs[buf][bkrow][bcol+2] = f2tf32(rb0.z);
        Bs[buf][bkrow][bcol+3] = f2tf32(rb0.w);
        Bs[buf][bkrow+8][bcol+0] = f2tf32(rb1.x);
        Bs[buf][bkrow+8][bcol+1] = f2tf32(rb1.y);
        Bs[buf][bkrow+8][bcol+2] = f2tf32(rb1.z);
        Bs[buf][bkrow+8][bcol+3] = f2tf32(rb1.w);
    };

    ldg(0); sts(0);
    __syncthreads();

    int nkt = K >> 4;
    for (int kt = 0; kt < nkt; kt++) {
        int buf = kt & 1;
        if (kt + 1 < nkt) ldg(kt + 1);

        #pragma unroll
        for (int ks = 0; ks < 2; ks++) {
            int kk = ks*8;
            unsigned af[2][4], bf[8][2];
            #pragma unroll
            for (int mi = 0; mi < 2; mi++) {
                int mr = wy*32 + mi*16 + g;
                af[mi][0] = As[buf][kk + t4][mr];
                af[mi][1] = As[buf][kk + t4][mr + 8];
                af[mi][2] = As[buf][kk + t4 + 4][mr];
                af[mi][3] = As[buf][kk + t4 + 4][mr + 8];
            }
            #pragma unroll
            for (int nj = 0; nj < 8; nj++) {
                int nc = wx*64 + nj*8 + g;
                bf[nj][0] = Bs[buf][kk + t4][nc];
                bf[nj][1] = Bs[buf][kk + t4 + 4][nc];
            }
            #pragma unroll
            for (int mi = 0; mi < 2; mi++)
                #pragma unroll
                for (int nj = 0; nj < 8; nj++)
                    mma_tf32(acc[mi][nj], af[mi], bf[nj]);
        }

        if (kt + 1 < nkt) sts(buf ^ 1);
        __syncthreads();
    }

    #pragma unroll
    for (int mi = 0; mi < 2; mi++) {
        #pragma unroll
        for (int nj = 0; nj < 8; nj++) {
            int row = m0 + wy*32 + mi*16 + g;
            int col = n0 + wx*64 + nj*8 + t4*2;
            float* p0 = &C[(long)row*N + col];
            float* p1 = &C[(long)(row+8)*N + col];
            float2 v0 = make_float2(acc[mi][nj][0], acc[mi][nj][1]);
            float2 v1 = make_float2(acc[mi][nj][2], acc[mi][nj][3]);
            if (accum) {
                float2 o0 = *(float2*)p0, o1 = *(float2*)p1;
                v0.x += o0.x; v0.y += o0.y; v1.x += o1.x; v1.y += o1.y;
            }
            *(float2*)p0 = v0;
            *(float2*)p1 = v1;
        }
    }
}

// ---------------- l2norm + scale, head-major ----------------
__global__ void norm_heads(const float* __restrict__ src, int srcStride, int colOff,
        int rowOff, const float* __restrict__ scale, float* __restrict__ dst, int nrows)
{
    int row = blockIdx.x, h = blockIdx.y, d = threadIdx.x;
    float v = src[(long)(rowOff+row)*srcStride + colOff + h*HD + d];
    float s = v*v;
    #pragma unroll
    for (int o = 16; o; o >>= 1) s += __shfl_xor_sync(0xffffffffu, s, o);
    __shared__ float sh[2];
    if ((d & 31) == 0) sh[d>>5] = s;
    __syncthreads();
    float inv = 1.f / fmaxf(sqrtf(sh[0]+sh[1]), 1e-12f);
    dst[((long)h*nrows + row)*HD + d] = v*inv*scale[d];
}

// ---------------- flash attention: Q frags in regs, K compensated, PV single ----------------
#define FPAD 68
#define TILEU (64*FPAD)
#define FLASH_SMEM (4*TILEU*4 + 256*4)

__global__ void __launch_bounds__(256, 2) flashmma(
        const float* __restrict__ Q, int qHeadRows,
        const float* __restrict__ Kh, int kHeadRows,
        const float* __restrict__ Vall, long vstride, int vColHeadMul, int vColAdd,
        int vRowExtra,
        const float* __restrict__ bias,
        float* __restrict__ Out, long ostride, int oColMul, int oColAdd,
        int L, int nwin)
{
    extern __shared__ unsigned usm[];
    unsigned* KHI = usm;                 // also Q-hi staging
    unsigned* KLO = usm + TILEU;         // also Q-lo staging
    unsigned* VS  = usm + 2*TILEU;
    unsigned* PT  = usm + 3*TILEU;
    float* SMAX = (float*)(usm + 4*TILEU);   // [64][2]
    float* SSUM = SMAX + 128;                // [64][2]

    int tid = threadIdx.x;
    int warp = tid >> 5, lane = tid & 31;
    int wy = warp >> 1, wx = warp & 1;
    int g = lane >> 2, t4 = lane & 3;

    int z = blockIdx.y;
    int h = z / nwin, w = z - h*nwin;
    int winw = qHeadRows / nwin;
    int i0 = blockIdx.x*64;
    int qrow0 = w*winw + i0;
    int kOff = (nwin > 1) ? (w-1)*winw : 0;

    const float* Qblk = Q + ((long)h*qHeadRows + qrow0)*64;
    const float* Kbase = Kh + (long)h*kHeadRows*64;
    const float* Vbase = Vall + vColHeadMul*h + vColAdd;
    const float* biasH = bias ? bias + (long)h*WIDTH*KEYW : nullptr;

    int mr = wy*16 + g;

    // ---- stage Q into SMEM (transposed, hi/lo), then preload fragments ----
    #pragma unroll
    for (int t = 0; t < 16; t++) {
        int e = tid + t*256;
        int r = e >> 6, c = e & 63;
        float v = Qblk[(long)r*64 + c];
        unsigned hi = f2tf32(v);
        KHI[c*FPAD + r] = hi;
        KLO[c*FPAD + r] = f2tf32(v - __uint_as_float(hi));
    }
    __syncthreads();

    unsigned aqhi[8][4], aqlo[8][4];
    #pragma unroll
    for (int ks = 0; ks < 8; ks++) {
        int kk = ks*8;
        aqhi[ks][0] = KHI[(kk+t4)*FPAD + mr];
        aqhi[ks][1] = KHI[(kk+t4)*FPAD + mr + 8];
        aqhi[ks][2] = KHI[(kk+t4+4)*FPAD + mr];
        aqhi[ks][3] = KHI[(kk+t4+4)*FPAD + mr + 8];
        aqlo[ks][0] = KLO[(kk+t4)*FPAD + mr];
        aqlo[ks][1] = KLO[(kk+t4)*FPAD + mr + 8];
        aqlo[ks][2] = KLO[(kk+t4+4)*FPAD + mr];
        aqlo[ks][3] = KLO[(kk+t4+4)*FPAD + mr + 8];
    }
    __syncthreads();

    float m0r = -3.402823466e38f, m1r = -3.402823466e38f;
    float l0 = 0.f, l1 = 0.f;
    float acc[4][4];
    #pragma unroll
    for (int nj = 0; nj < 4; nj++)
        #pragma unroll
        for (int c = 0; c < 4; c++) acc[nj][c] = 0.f;

    int Lq = biasH ? (i0 + 576) : L;
    if (Lq > L) Lq = L;

    for (int c0 = 0; c0 < Lq; c0 += 64) {
        // load + split K [d][key]; V single [key][d]
        #pragma unroll
        for (int t = 0; t < 16; t++) {
            int e = tid + t*256;
            int r = e >> 6, cc = e & 63;
            int kr = kOff + c0 + r;
            float kv = (kr >= 0) ? Kbase[(long)kr*64 + cc] : 0.f;
            float vv = (kr >= 0) ? Vbase[(long)(kr + vRowExtra)*vstride + cc] : 0.f;
            unsigned khi = f2tf32(kv);
            KHI[cc*FPAD + r] = khi;
            KLO[cc*FPAD + r] = f2tf32(kv - __uint_as_float(khi));
            VS[r*FPAD + cc] = f2tf32(vv);
        }
        __syncthreads();

        // ---- S = Q @ K^T (compensated; Q frags already in regs) ----
        float sf[4][4];
        #pragma unroll
        for (int nj = 0; nj < 4; nj++)
            #pragma unroll
            for (int c = 0; c < 4; c++) sf[nj][c] = 0.f;

        #pragma unroll
        for (int ks = 0; ks < 8; ks++) {
            int kk = ks*8;
            #pragma unroll
            for (int nj = 0; nj < 4; nj++) {
                int nc = wx*32 + nj*8 + g;
                unsigned bhi[2] = { KHI[(kk+t4)*FPAD + nc], KHI[(kk+t4+4)*FPAD + nc] };
                unsigned blo[2] = { KLO[(kk+t4)*FPAD + nc], KLO[(kk+t4+4)*FPAD + nc] };
                mma_tf32(sf[nj], aqhi[ks], bhi);
                mma_tf32(sf[nj], aqlo[ks], bhi);
                mma_tf32(sf[nj], aqhi[ks], blo);
            }
        }

        // ---- scale + bias + mask ----
        int ir0 = i0 + mr, ir1 = ir0 + 8;
        #pragma unroll
        for (int nj = 0; nj < 4; nj++) {
            int j0 = c0 + wx*32 + nj*8 + 2*t4;
            #pragma unroll
            for (int c = 0; c < 4; c++) sf[nj][c] *= 8.f;
            if (biasH) {
                float2 b0 = *(const float2*)&biasH[(long)ir0*KEYW + j0];
                float2 b1 = *(const float2*)&biasH[(long)ir1*KEYW + j0];
                sf[nj][0] += b0.x; sf[nj][1] += b0.y;
                sf[nj][2] += b1.x; sf[nj][3] += b1.y;
                if (j0     > ir0 + 512) sf[nj][0] = -3.402823466e38f;
                if (j0 + 1 > ir0 + 512) sf[nj][1] = -3.402823466e38f;
                if (j0     > ir1 + 512) sf[nj][2] = -3.402823466e38f;
                if (j0 + 1 > ir1 + 512) sf[nj][3] = -3.402823466e38f;
            }
        }

        // ---- row max ----
        float pm0 = -3.402823466e38f, pm1 = -3.402823466e38f;
        #pragma unroll
        for (int nj = 0; nj < 4; nj++) {
            pm0 = fmaxf(pm0, fmaxf(sf[nj][0], sf[nj][1]));
            pm1 = fmaxf(pm1, fmaxf(sf[nj][2], sf[nj][3]));
        }
        pm0 = fmaxf(pm0, __shfl_xor_sync(0xffffffffu, pm0, 1));
        pm0 = fmaxf(pm0, __shfl_xor_sync(0xffffffffu, pm0, 2));
        pm1 = fmaxf(pm1, __shfl_xor_sync(0xffffffffu, pm1, 1));
        pm1 = fmaxf(pm1, __shfl_xor_sync(0xffffffffu, pm1, 2));
        if (t4 == 0) {
            SMAX[mr*2 + wx] = pm0;
            SMAX[(mr+8)*2 + wx] = pm1;
        }
        __syncthreads();
        float cmax0 = fmaxf(SMAX[mr*2], SMAX[mr*2+1]);
        float cmax1 = fmaxf(SMAX[(mr+8)*2], SMAX[(mr+8)*2+1]);

        float mn0 = fmaxf(m0r, cmax0);
        float mn1 = fmaxf(m1r, cmax1);
        float corr0 = __expf(m0r - mn0);
        float corr1 = __expf(m1r - mn1);
        m0r = mn0; m1r = mn1;

        // exp + partial sums + write P transposed [key][row]
        float ps0 = 0.f, ps1 = 0.f;
        #pragma unroll
        for (int nj = 0; nj < 4; nj++) {
            int j0 = wx*32 + nj*8 + 2*t4;
            float p00 = __expf(sf[nj][0] - mn0);
            float p01 = __expf(sf[nj][1] - mn0);
            float p10 = __expf(sf[nj][2] - mn1);
            float p11 = __expf(sf[nj][3] - mn1);
            ps0 += p00 + p01;
            ps1 += p10 + p11;
            PT[j0*FPAD + mr]       = f2tf32(p00);
            PT[(j0+1)*FPAD + mr]   = f2tf32(p01);
            PT[j0*FPAD + mr+8]     = f2tf32(p10);
            PT[(j0+1)*FPAD + mr+8] = f2tf32(p11);
        }
        ps0 += __shfl_xor_sync(0xffffffffu, ps0, 1);
        ps0 += __shfl_xor_sync(0xffffffffu, ps0, 2);
        ps1 += __shfl_xor_sync(0xffffffffu, ps1, 1);
        ps1 += __shfl_xor_sync(0xffffffffu, ps1, 2);
        if (t4 == 0) {
            SSUM[mr*2 + wx] = ps0;
            SSUM[(mr+8)*2 + wx] = ps1;
        }

        // rescale accumulators
        #pragma unroll
        for (int nj = 0; nj < 4; nj++) {
            acc[nj][0] *= corr0; acc[nj][1] *= corr0;
            acc[nj][2] *= corr1; acc[nj][3] *= corr1;
        }
        __syncthreads();

        l0 = l0*corr0 + SSUM[mr*2] + SSUM[mr*2+1];
        l1 = l1*corr1 + SSUM[(mr+8)*2] + SSUM[(mr+8)*2+1];

        // ---- acc += P @ V (single tf32) ----
        #pragma unroll
        for (int kk = 0; kk < 64; kk += 8) {
            unsigned ap[4];
            ap[0] = PT[(kk+t4)*FPAD + mr];
            ap[1] = PT[(kk+t4)*FPAD + mr + 8];
            ap[2] = PT[(kk+t4+4)*FPAD + mr];
            ap[3] = PT[(kk+t4+4)*FPAD + mr + 8];
            #pragma unroll
            for (int nj = 0; nj < 4; nj++) {
                int nc = wx*32 + nj*8 + g;
                unsigned bv[2] = { VS[(kk+t4)*FPAD + nc], VS[(kk+t4+4)*FPAD + nc] };
                mma_tf32(acc[nj], ap, bv);
            }
        }
        __syncthreads();
    }

    // epilogue
    float inv0 = 1.f / l0, inv1 = 1.f / l1;
    #pragma unroll
    for (int nj = 0; nj < 4; nj++) {
        int col = h*oColMul + oColAdd + wx*32 + nj*8 + 2*t4;
        long r0 = (long)(qrow0 + mr)*ostride + col;
        long r1 = (long)(qrow0 + mr + 8)*ostride + col;
        *(float2*)&Out[r0] = make_float2(acc[nj][0]*inv0, acc[nj][1]*inv0);
        *(float2*)&Out[r1] = make_float2(acc[nj][2]*inv1, acc[nj][3]*inv1);
    }
}

// ---------------- memories copy ----------------
__global__ void memories_kernel(const float* __restrict__ qkv, float* __restrict__ out)
{
    int idx = blockIdx.x*256 + threadIdx.x;
    if (idx >= 2*HEADS*WIDTH*HD) return;
    int d = idx & 63;
    int i = (idx >> 6) & 511;
    int h = (idx >> 15) & 15;
    int s = idx >> 19;
    out[idx] = qkv[(long)(3584+i)*3072 + (s ? 2048 : 1024) + h*HD + d];
}

// ---------------- new_states ----------------
__global__ void newstates_kernel(const float* __restrict__ gz, const float* __restrict__ bg,
        const float* __restrict__ beta, const float* __restrict__ init_state,
        float* __restrict__ out)
{
    int idx = blockIdx.x*256 + threadIdx.x;
    if (idx >= NST*DIMM) return;
    int c = idx & (DIMM-1);
    float sig = 1.f/(1.f+expf(-beta[c]));
    float z = gz[idx] + bg[c];
    out[idx] = sig*z + (1.f-sig)*init_state[idx];
}

// ---------------- host launch ----------------
static float* symaddr(const void* s)
{
    void* p = nullptr;
    cudaGetSymbolAddress(&p, s);
    return (float*)p;
}

extern "C" void kernel_launch(void* const* d_in, const int* in_sizes, int n_in,
                              void* d_out, int out_size)
{
    const float* x       = (const float*)d_in[0];
    const float* bias    = (const float*)d_in[1];
    const float* gamma   = (const float*)d_in[2];
    const float* w_qkv   = (const float*)d_in[3];
    const float* q_scale = (const float*)d_in[4];
    const float* k_scale = (const float*)d_in[5];
    const float* w_out   = (const float*)d_in[6];
    const float* s_gamma = (const float*)d_in[7];
    const float* w_q2s   = (const float*)d_in[8];
    const float* w_qfs   = (const float*)d_in[9];
    const float* w_sqkv  = (const float*)d_in[10];
    const float* init_st = (const float*)d_in[11];
    const float* pos_ids = (const float*)d_in[12];
    const float* w_sout  = (const float*)d_in[13];
    const float* ts_q    = (const float*)d_in[14];
    const float* ts_k    = (const float*)d_in[15];
    const float* ss_q    = (const float*)d_in[16];
    const float* ss_k    = (const float*)d_in[17];
    const float* fs_q    = (const float*)d_in[18];
    const float* fs_k    = (const float*)d_in[19];
    const float* w_gate  = (const float*)d_in[20];
    const float* b_gate  = (const float*)d_in[21];
    const float* beta    = (const float*)d_in[22];
    float* out = (float*)d_out;

    float* xn   = symaddr(g_xn);
    float* qkv  = symaddr(g_qkv);
    float* q2s  = symaddr(g_q2s);
    float* sqkv = symaddr(g_state_qkv);
    float* st   = symaddr(g_st);
    float* qfsr = symaddr(g_qfs_raw);
    float* qnm  = symaddr(g_qn_main);
    float* knm  = symaddr(g_kn_main);
    float* qnts = symaddr(g_qn_ts);
    float* knts = symaddr(g_kn_ts);
    float* qnss = symaddr(g_qn_ss);
    float* knss = symaddr(g_kn_ss);
    float* qnfs = symaddr(g_qn_fs);
    float* knfs = symaddr(g_kn_fs);
    float* aout = symaddr(g_attn_out);
    float* tout = symaddr(g_ts_out);
    float* scat = symaddr(g_state_cat);
    float* so   = symaddr(g_so);
    float* zb   = symaddr(g_z);

    cudaFuncSetAttribute(flashmma, cudaFuncAttributeMaxDynamicSharedMemorySize, FLASH_SMEM);

    // 1) layernorms
    ln_kernel<<<NSEQ, 256>>>(x, gamma, nullptr, xn);
    ln_kernel<<<NST, 256>>>(init_st, s_gamma, pos_ids, st);

    // 2) projections (TF32 tensor cores)
    tgemm<<<dim3(3072/128, NSEQ/128), 256>>>(xn, w_qkv, qkv, NSEQ, 3072, DIMM, 0);
    tgemm<<<dim3(DIMM/128, NSEQ/128), 256>>>(xn, w_q2s, q2s, NSEQ, DIMM, DIMM, 0);
    tgemm<<<dim3(3072/128, NST/128), 256>>>(init_st, w_sqkv, sqkv, NST, 3072, DIMM, 0);
    tgemm<<<dim3(DIMM/128, NST/128), 256>>>(st, w_qfs, qfsr, NST, DIMM, DIMM, 0);

    // 3) l2norm + scale, head-major
    norm_heads<<<dim3(NSEQ, HEADS), 64>>>(qkv, 3072, 0,    0,    q_scale, qnm,  NSEQ);
    norm_heads<<<dim3(NSEQ, HEADS), 64>>>(qkv, 3072, 1024, 0,    k_scale, knm,  NSEQ);
    norm_heads<<<dim3(NSEQ, HEADS), 64>>>(q2s, 1024, 0,    0,    ts_q,    qnts, NSEQ);
    norm_heads<<<dim3(NST,  HEADS), 64>>>(sqkv, 3072, 1024, 0,   ts_k,    knts, NST);
    norm_heads<<<dim3(NST,  HEADS), 64>>>(sqkv, 3072, 0,    0,   ss_q,    qnss, NST);
    norm_heads<<<dim3(NST,  HEADS), 64>>>(sqkv, 3072, 1024, 0,   ss_k,    knss, NST);
    norm_heads<<<dim3(NST,  HEADS), 64>>>(qfsr, 1024, 0,    0,   fs_q,    qnfs, NST);
    norm_heads<<<dim3(NST,  HEADS), 64>>>(qkv,  3072, 1024, 3584, fs_k,   knfs, NST);

    // 4) fused attentions
    flashmma<<<dim3(WIDTH/64, HEADS*NW), 256, FLASH_SMEM>>>(
        qnm, NSEQ, knm, NSEQ, qkv, 3072, HD, 2048, 0, bias,
        aout, DIMM, HD, 0, KEYW, NW);
    flashmma<<<dim3(NSEQ/64, HEADS), 256, FLASH_SMEM>>>(
        qnts, NSEQ, knts, NST, sqkv, 3072, HD, 2048, 0, nullptr,
        tout, DIMM, HD, 0, NST, 1);
    flashmma<<<dim3(NST/64, HEADS), 256, FLASH_SMEM>>>(
        qnss, NST, knss, NST, sqkv, 3072, HD, 2048, 0, nullptr,
        scat, 2*DIMM, 2*HD, 0, NST, 1);
    flashmma<<<dim3(NST/64, HEADS), 256, FLASH_SMEM>>>(
        qnfs, NST, knfs, NST, qkv, 3072, HD, 2048, 3584, nullptr,
        scat, 2*DIMM, 2*HD, HD, NST, 1);

    // 5) output projections
    tgemm<<<dim3(DIMM/128, NSEQ/128), 256>>>(aout, w_out, out, NSEQ, DIMM, DIMM, 0);
    tgemm<<<dim3(DIMM/128, NSEQ/128), 256>>>(tout, w_out + (long)DIMM*DIMM, out, NSEQ, DIMM, DIMM, 1);

    // 6) memories
    memories_kernel<<<(2*HEADS*WIDTH*HD)/256, 256>>>(qkv, out + (long)NSEQ*DIMM);

    // 7) state output path
    tgemm<<<dim3(DIMM/128, NST/128), 256>>>(scat, w_sout, so, NST, DIMM, 2*DIMM, 0);
    tgemm<<<dim3(DIMM/128, NST/128), 256>>>(so, w_gate, zb, NST, DIMM, DIMM, 0);
    newstates_kernel<<<(NST*DIMM)/256, 256>>>(zb, b_gate, beta, init_st,
            out + (long)NSEQ*DIMM + 2*HEADS*WIDTH*HD);
}

// round 7
// speedup vs baseline: 1.4151x; 1.2108x over previous
#include <cuda_runtime.h>
#include <math.h>

#define NSEQ  4096
#define DIMM  1024
#define HEADS 16
#define HD    64
#define WIDTH 512
#define NW    8
#define NST   512
#define KEYW  1024

// ---------------- scratch ----------------
__device__ float g_xn[NSEQ*DIMM];
__device__ float g_qkv[NSEQ*3*DIMM];
__device__ float g_q2s[NSEQ*DIMM];
__device__ float g_state_qkv[NST*3*DIMM];
__device__ float g_st[NST*DIMM];
__device__ float g_qfs_raw[NST*DIMM];

__device__ float g_qn_main[HEADS*NSEQ*HD];
__device__ float g_kn_main[HEADS*NSEQ*HD];
__device__ float g_qn_ts[HEADS*NSEQ*HD];
__device__ float g_kn_ts[HEADS*NST*HD];
__device__ float g_qn_ss[HEADS*NST*HD];
__device__ float g_kn_ss[HEADS*NST*HD];
__device__ float g_qn_fs[HEADS*NST*HD];
__device__ float g_kn_fs[HEADS*NST*HD];

__device__ float g_attn_out[NSEQ*DIMM];
__device__ float g_ts_out[NSEQ*DIMM];
__device__ float g_state_cat[NST*2*DIMM];
__device__ float g_so[NST*DIMM];
__device__ float g_z[NST*DIMM];

// ---------------- layernorm ----------------
__global__ void __launch_bounds__(256) ln_kernel(const float* __restrict__ x,
        const float* __restrict__ gamma, const float* __restrict__ pos,
        float* __restrict__ out)
{
    int row = blockIdx.x;
    const float* xr = x + (long)row*DIMM;
    float* orow = out + (long)row*DIMM;
    __shared__ float red[256];
    float s = 0.f, s2 = 0.f;
    for (int i = threadIdx.x; i < DIMM; i += 256) { float v = xr[i]; s += v; s2 += v*v; }
    red[threadIdx.x] = s; __syncthreads();
    for (int o = 128; o; o >>= 1) { if (threadIdx.x < o) red[threadIdx.x] += red[threadIdx.x+o]; __syncthreads(); }
    float mu = red[0] * (1.f/DIMM);
    __syncthreads();
    red[threadIdx.x] = s2; __syncthreads();
    for (int o = 128; o; o >>= 1) { if (threadIdx.x < o) red[threadIdx.x] += red[threadIdx.x+o]; __syncthreads(); }
    float var = red[0] * (1.f/DIMM) - mu*mu;
    float inv = rsqrtf(var + 1e-5f);
    for (int i = threadIdx.x; i < DIMM; i += 256) {
        float v = (xr[i]-mu)*inv*gamma[i];
        if (pos) v += pos[(long)row*DIMM + i];
        orow[i] = v;
    }
}

// ---------------- TF32 helpers ----------------
__device__ __forceinline__ unsigned f2tf32(float f)
{
    unsigned r;
    asm("cvt.rna.tf32.f32 %0, %1;" : "=r"(r) : "f"(f));
    return r;
}

__device__ __forceinline__ void mma_tf32(float c[4], const unsigned a[4], const unsigned b[2])
{
    asm volatile(
        "mma.sync.aligned.m16n8k8.row.col.f32.tf32.tf32.f32 "
        "{%0,%1,%2,%3}, {%4,%5,%6,%7}, {%8,%9}, {%0,%1,%2,%3};"
        : "+f"(c[0]), "+f"(c[1]), "+f"(c[2]), "+f"(c[3])
        : "r"(a[0]), "r"(a[1]), "r"(a[2]), "r"(a[3]), "r"(b[0]), "r"(b[1]));
}

// ---------------- TF32 tensor-core GEMM ----------------
__global__ void __launch_bounds__(256) tgemm(const float* __restrict__ A,
        const float* __restrict__ B, float* __restrict__ C,
        int M, int N, int K, int accum)
{
    __shared__ unsigned As[2][16][132];
    __shared__ unsigned Bs[2][16][132];

    int tid = threadIdx.x;
    int warp = tid >> 5, lane = tid & 31;
    int wy = warp >> 1, wx = warp & 1;
    int g = lane >> 2, t4 = lane & 3;
    int m0 = blockIdx.y*128, n0 = blockIdx.x*128;

    int arow = tid >> 2;
    int acol = (tid & 3) * 4;
    int bkrow = tid >> 5;
    int bcol = lane * 4;

    const float* Abase = A + (long)(m0 + arow)*K + acol;
    const float* Bbase = B + (long)bkrow*N + n0 + bcol;

    float acc[2][8][4];
    #pragma unroll
    for (int mi = 0; mi < 2; mi++)
        #pragma unroll
        for (int nj = 0; nj < 8; nj++)
            #pragma unroll
            for (int c = 0; c < 4; c++) acc[mi][nj][c] = 0.f;

    float4 ra0, ra1, rb0, rb1;

    auto ldg = [&](int kt) {
        ra0 = *(const float4*)(Abase + kt*16);
        ra1 = *(const float4*)(Abase + kt*16 + (long)64*K);
        rb0 = *(const float4*)(Bbase + (long)kt*16*N);
        rb1 = *(const float4*)(Bbase + (long)(kt*16+8)*N);
    };
    auto sts = [&](int buf) {
        As[buf][acol+0][arow] = f2tf32(ra0.x);
        As[buf][acol+1][arow] = f2tf32(ra0.y);
        As[buf][acol+2][arow] = f2tf32(ra0.z);
        As[buf][acol+3][arow] = f2tf32(ra0.w);
        As[buf][acol+0][arow+64] = f2tf32(ra1.x);
        As[buf][acol+1][arow+64] = f2tf32(ra1.y);
        As[buf][acol+2][arow+64] = f2tf32(ra1.z);
        As[buf][acol+3][arow+64] = f2tf32(ra1.w);
        Bs[buf][bkrow][bcol+0] = f2tf32(rb0.x);
        Bs[buf][bkrow][bcol+1] = f2tf32(rb0.y);
        Bs[buf][bkrow][bcol+2] = f2tf32(rb0.z);
        Bs[buf][bkrow][bcol+3] = f2tf32(rb0.w);
        Bs[buf][bkrow+8][bcol+0] = f2tf32(rb1.x);
        Bs[buf][bkrow+8][bcol+1] = f2tf32(rb1.y);
        Bs[buf][bkrow+8][bcol+2] = f2tf32(rb1.z);
        Bs[buf][bkrow+8][bcol+3] = f2tf32(rb1.w);
    };

    ldg(0); sts(0);
    __syncthreads();

    int nkt = K >> 4;
    for (int kt = 0; kt < nkt; kt++) {
        int buf = kt & 1;
        if (kt + 1 < nkt) ldg(kt + 1);

        #pragma unroll
        for (int ks = 0; ks < 2; ks++) {
            int kk = ks*8;
            unsigned af[2][4], bf[8][2];
            #pragma unroll
            for (int mi = 0; mi < 2; mi++) {
                int mr = wy*32 + mi*16 + g;
                af[mi][0] = As[buf][kk + t4][mr];
                af[mi][1] = As[buf][kk + t4][mr + 8];
                af[mi][2] = As[buf][kk + t4 + 4][mr];
                af[mi][3] = As[buf][kk + t4 + 4][mr + 8];
            }
            #pragma unroll
            for (int nj = 0; nj < 8; nj++) {
                int nc = wx*64 + nj*8 + g;
                bf[nj][0] = Bs[buf][kk + t4][nc];
                bf[nj][1] = Bs[buf][kk + t4 + 4][nc];
            }
            #pragma unroll
            for (int mi = 0; mi < 2; mi++)
                #pragma unroll
                for (int nj = 0; nj < 8; nj++)
                    mma_tf32(acc[mi][nj], af[mi], bf[nj]);
        }

        if (kt + 1 < nkt) sts(buf ^ 1);
        __syncthreads();
    }

    #pragma unroll
    for (int mi = 0; mi < 2; mi++) {
        #pragma unroll
        for (int nj = 0; nj < 8; nj++) {
            int row = m0 + wy*32 + mi*16 + g;
            int col = n0 + wx*64 + nj*8 + t4*2;
            float* p0 = &C[(long)row*N + col];
            float* p1 = &C[(long)(row+8)*N + col];
            float2 v0 = make_float2(acc[mi][nj][0], acc[mi][nj][1]);
            float2 v1 = make_float2(acc[mi][nj][2], acc[mi][nj][3]);
            if (accum) {
                float2 o0 = *(float2*)p0, o1 = *(float2*)p1;
                v0.x += o0.x; v0.y += o0.y; v1.x += o1.x; v1.y += o1.y;
            }
            *(float2*)p0 = v0;
            *(float2*)p1 = v1;
        }
    }
}

// ---------------- l2norm + scale, head-major ----------------
__global__ void norm_heads(const float* __restrict__ src, int srcStride, int colOff,
        int rowOff, const float* __restrict__ scale, float* __restrict__ dst, int nrows)
{
    int row = blockIdx.x, h = blockIdx.y, d = threadIdx.x;
    float v = src[(long)(rowOff+row)*srcStride + colOff + h*HD + d];
    float s = v*v;
    #pragma unroll
    for (int o = 16; o; o >>= 1) s += __shfl_xor_sync(0xffffffffu, s, o);
    __shared__ float sh[2];
    if ((d & 31) == 0) sh[d>>5] = s;
    __syncthreads();
    float inv = 1.f / fmaxf(sqrtf(sh[0]+sh[1]), 1e-12f);
    dst[((long)h*nrows + row)*HD + d] = v*inv*scale[d];
}

// ---------------- fused flash attention (scalar fp32, 64-row q tiles) ----------------
__global__ void __launch_bounds__(256) flash64(
        const float* __restrict__ Q, int qHeadRows,
        const float* __restrict__ Kh, int kHeadRows,
        const float* __restrict__ Vall, long vstride, int vColHeadMul, int vColAdd,
        int vRowExtra,
        const float* __restrict__ bias,
        float* __restrict__ Out, long ostride, int oColMul, int oColAdd,
        int L, int nwin)
{
    extern __shared__ float sm[];
    float (*Qs)[68] = (float(*)[68])(sm);
    float (*Ks)[68] = (float(*)[68])(sm + 64*68);
    float (*Vs)[68] = (float(*)[68])(sm + 2*64*68);
    float (*Ps)[68] = (float(*)[68])(sm + 3*64*68);

    int tid = threadIdx.x;
    int tx = tid & 15, ty = tid >> 4;

    int z = blockIdx.y;
    int h = z / nwin, w = z - h*nwin;
    int winw = qHeadRows / nwin;
    int i0 = blockIdx.x*64;
    int qrow0 = w*winw + i0;
    int kOff = (nwin > 1) ? (w-1)*winw : 0;

    const float* Qblk = Q + ((long)h*qHeadRows + qrow0)*64;
    const float* Kbase = Kh + (long)h*kHeadRows*64;
    const float* Vbase = Vall + vColHeadMul*h + vColAdd;
    const float* biasH = bias ? bias + (long)h*WIDTH*KEYW : nullptr;

    #pragma unroll
    for (int t = 0; t < 16; t++) {
        int e = tid + t*256;
        int r = e >> 6, c = e & 63;
        Qs[c][r] = Qblk[(long)r*64 + c];
    }

    float m[4], l[4], acc[4][4];
    #pragma unroll
    for (int i = 0; i < 4; i++) {
        m[i] = -3.402823466e38f; l[i] = 0.f;
        #pragma unroll
        for (int j = 0; j < 4; j++) acc[i][j] = 0.f;
    }

    // causal chunk skip: columns j > i_local + 512 are masked; last useful chunk
    // for this tile ends at i0 + 63 + 512 -> stop at i0 + 576.
    int Lq = biasH ? (i0 + 576) : L;
    if (Lq > L) Lq = L;

    for (int c0 = 0; c0 < Lq; c0 += 64) {
        #pragma unroll
        for (int t = 0; t < 16; t++) {
            int e = tid + t*256;
            int r = e >> 6, cc = e & 63;
            int kr = kOff + c0 + r;
            Ks[cc][r] = (kr >= 0) ? Kbase[(long)kr*64 + cc] : 0.f;
            Vs[r][cc] = (kr >= 0) ? Vbase[(long)(kr + vRowExtra)*vstride + cc] : 0.f;
        }
        __syncthreads();

        float s[4][4];
        #pragma unroll
        for (int i = 0; i < 4; i++)
            #pragma unroll
            for (int j = 0; j < 4; j++) s[i][j] = 0.f;
        #pragma unroll
        for (int kk = 0; kk < 64; kk++) {
            float a[4], b[4];
            #pragma unroll
            for (int i = 0; i < 4; i++) a[i] = Qs[kk][ty*4+i];
            #pragma unroll
            for (int j = 0; j < 4; j++) b[j] = Ks[kk][tx*4+j];
            #pragma unroll
            for (int i = 0; i < 4; i++)
                #pragma unroll
                for (int j = 0; j < 4; j++)
                    s[i][j] += a[i]*b[j];
        }

        #pragma unroll
        for (int i = 0; i < 4; i++) {
            int irow = i0 + ty*4 + i;
            #pragma unroll
            for (int j = 0; j < 4; j++) {
                int jcol = c0 + tx*4 + j;
                float v = s[i][j]*8.f;
                if (biasH) {
                    v += biasH[(long)irow*KEYW + jcol];
                    if (jcol > irow + 512) v = -3.402823466e38f;
                }
                s[i][j] = v;
            }
        }

        #pragma unroll
        for (int i = 0; i < 4; i++) {
            float cm = fmaxf(fmaxf(s[i][0], s[i][1]), fmaxf(s[i][2], s[i][3]));
            #pragma unroll
            for (int o = 8; o; o >>= 1) cm = fmaxf(cm, __shfl_xor_sync(0xffffffffu, cm, o));
            float mnew = fmaxf(m[i], cm);
            float corr = __expf(m[i] - mnew);
            l[i] *= corr;
            #pragma unroll
            for (int j = 0; j < 4; j++) acc[i][j] *= corr;
            float rs = 0.f;
            #pragma unroll
            for (int j = 0; j < 4; j++) {
                float p = __expf(s[i][j] - mnew);
                s[i][j] = p;
                rs += p;
            }
            #pragma unroll
            for (int o = 8; o; o >>= 1) rs += __shfl_xor_sync(0xffffffffu, rs, o);
            l[i] += rs;
            m[i] = mnew;
            Ps[ty*4+i][tx*4+0] = s[i][0];
            Ps[ty*4+i][tx*4+1] = s[i][1];
            Ps[ty*4+i][tx*4+2] = s[i][2];
            Ps[ty*4+i][tx*4+3] = s[i][3];
        }
        __syncthreads();

        #pragma unroll
        for (int kk = 0; kk < 64; kk++) {
            float a[4], b[4];
            #pragma unroll
            for (int i = 0; i < 4; i++) a[i] = Ps[ty*4+i][kk];
            #pragma unroll
            for (int j = 0; j < 4; j++) b[j] = Vs[kk][tx*4+j];
            #pragma unroll
            for (int i = 0; i < 4; i++)
                #pragma unroll
                for (int j = 0; j < 4; j++)
                    acc[i][j] += a[i]*b[j];
        }
        __syncthreads();
    }

    #pragma unroll
    for (int i = 0; i < 4; i++) {
        float inv = 1.f / l[i];
        long orow = (long)(qrow0 + ty*4 + i)*ostride + h*oColMul + oColAdd + tx*4;
        #pragma unroll
        for (int j = 0; j < 4; j++)
            Out[orow + j] = acc[i][j]*inv;
    }
}

// ---------------- memories copy ----------------
__global__ void memories_kernel(const float* __restrict__ qkv, float* __restrict__ out)
{
    int idx = blockIdx.x*256 + threadIdx.x;
    if (idx >= 2*HEADS*WIDTH*HD) return;
    int d = idx & 63;
    int i = (idx >> 6) & 511;
    int h = (idx >> 15) & 15;
    int s = idx >> 19;
    out[idx] = qkv[(long)(3584+i)*3072 + (s ? 2048 : 1024) + h*HD + d];
}

// ---------------- new_states ----------------
__global__ void newstates_kernel(const float* __restrict__ gz, const float* __restrict__ bg,
        const float* __restrict__ beta, const float* __restrict__ init_state,
        float* __restrict__ out)
{
    int idx = blockIdx.x*256 + threadIdx.x;
    if (idx >= NST*DIMM) return;
    int c = idx & (DIMM-1);
    float sig = 1.f/(1.f+expf(-beta[c]));
    float z = gz[idx] + bg[c];
    out[idx] = sig*z + (1.f-sig)*init_state[idx];
}

// ---------------- host launch ----------------
static float* symaddr(const void* s)
{
    void* p = nullptr;
    cudaGetSymbolAddress(&p, s);
    return (float*)p;
}

#define FLASH_SMEM (4*64*68*4)

extern "C" void kernel_launch(void* const* d_in, const int* in_sizes, int n_in,
                              void* d_out, int out_size)
{
    const float* x       = (const float*)d_in[0];
    const float* bias    = (const float*)d_in[1];
    const float* gamma   = (const float*)d_in[2];
    const float* w_qkv   = (const float*)d_in[3];
    const float* q_scale = (const float*)d_in[4];
    const float* k_scale = (const float*)d_in[5];
    const float* w_out   = (const float*)d_in[6];
    const float* s_gamma = (const float*)d_in[7];
    const float* w_q2s   = (const float*)d_in[8];
    const float* w_qfs   = (const float*)d_in[9];
    const float* w_sqkv  = (const float*)d_in[10];
    const float* init_st = (const float*)d_in[11];
    const float* pos_ids = (const float*)d_in[12];
    const float* w_sout  = (const float*)d_in[13];
    const float* ts_q    = (const float*)d_in[14];
    const float* ts_k    = (const float*)d_in[15];
    const float* ss_q    = (const float*)d_in[16];
    const float* ss_k    = (const float*)d_in[17];
    const float* fs_q    = (const float*)d_in[18];
    const float* fs_k    = (const float*)d_in[19];
    const float* w_gate  = (const float*)d_in[20];
    const float* b_gate  = (const float*)d_in[21];
    const float* beta    = (const float*)d_in[22];
    float* out = (float*)d_out;

    float* xn   = symaddr(g_xn);
    float* qkv  = symaddr(g_qkv);
    float* q2s  = symaddr(g_q2s);
    float* sqkv = symaddr(g_state_qkv);
    float* st   = symaddr(g_st);
    float* qfsr = symaddr(g_qfs_raw);
    float* qnm  = symaddr(g_qn_main);
    float* knm  = symaddr(g_kn_main);
    float* qnts = symaddr(g_qn_ts);
    float* knts = symaddr(g_kn_ts);
    float* qnss = symaddr(g_qn_ss);
    float* knss = symaddr(g_kn_ss);
    float* qnfs = symaddr(g_qn_fs);
    float* knfs = symaddr(g_kn_fs);
    float* aout = symaddr(g_attn_out);
    float* tout = symaddr(g_ts_out);
    float* scat = symaddr(g_state_cat);
    float* so   = symaddr(g_so);
    float* zb   = symaddr(g_z);

    cudaFuncSetAttribute(flash64, cudaFuncAttributeMaxDynamicSharedMemorySize, FLASH_SMEM);

    // 1) layernorms
    ln_kernel<<<NSEQ, 256>>>(x, gamma, nullptr, xn);
    ln_kernel<<<NST, 256>>>(init_st, s_gamma, pos_ids, st);

    // 2) projections (TF32 tensor cores)
    tgemm<<<dim3(3072/128, NSEQ/128), 256>>>(xn, w_qkv, qkv, NSEQ, 3072, DIMM, 0);
    tgemm<<<dim3(DIMM/128, NSEQ/128), 256>>>(xn, w_q2s, q2s, NSEQ, DIMM, DIMM, 0);
    tgemm<<<dim3(3072/128, NST/128), 256>>>(init_st, w_sqkv, sqkv, NST, 3072, DIMM, 0);
    tgemm<<<dim3(DIMM/128, NST/128), 256>>>(st, w_qfs, qfsr, NST, DIMM, DIMM, 0);

    // 3) l2norm + scale, head-major
    norm_heads<<<dim3(NSEQ, HEADS), 64>>>(qkv, 3072, 0,    0,    q_scale, qnm,  NSEQ);
    norm_heads<<<dim3(NSEQ, HEADS), 64>>>(qkv, 3072, 1024, 0,    k_scale, knm,  NSEQ);
    norm_heads<<<dim3(NSEQ, HEADS), 64>>>(q2s, 1024, 0,    0,    ts_q,    qnts, NSEQ);
    norm_heads<<<dim3(NST,  HEADS), 64>>>(sqkv, 3072, 1024, 0,   ts_k,    knts, NST);
    norm_heads<<<dim3(NST,  HEADS), 64>>>(sqkv, 3072, 0,    0,   ss_q,    qnss, NST);
    norm_heads<<<dim3(NST,  HEADS), 64>>>(sqkv, 3072, 1024, 0,   ss_k,    knss, NST);
    norm_heads<<<dim3(NST,  HEADS), 64>>>(qfsr, 1024, 0,    0,   fs_q,    qnfs, NST);
    norm_heads<<<dim3(NST,  HEADS), 64>>>(qkv,  3072, 1024, 3584, fs_k,   knfs, NST);

    // 4) fused attentions (scalar flash + causal chunk skip)
    flash64<<<dim3(WIDTH/64, HEADS*NW), 256, FLASH_SMEM>>>(
        qnm, NSEQ, knm, NSEQ, qkv, 3072, HD, 2048, 0, bias,
        aout, DIMM, HD, 0, KEYW, NW);
    flash64<<<dim3(NSEQ/64, HEADS), 256, FLASH_SMEM>>>(
        qnts, NSEQ, knts, NST, sqkv, 3072, HD, 2048, 0, nullptr,
        tout, DIMM, HD, 0, NST, 1);
    flash64<<<dim3(NST/64, HEADS), 256, FLASH_SMEM>>>(
        qnss, NST, knss, NST, sqkv, 3072, HD, 2048, 0, nullptr,
        scat, 2*DIMM, 2*HD, 0, NST, 1);
    flash64<<<dim3(NST/64, HEADS), 256, FLASH_SMEM>>>(
        qnfs, NST, knfs, NST, qkv, 3072, HD, 2048, 3584, nullptr,
        scat, 2*DIMM, 2*HD, HD, NST, 1);

    // 5) output projections
    tgemm<<<dim3(DIMM/128, NSEQ/128), 256>>>(aout, w_out, out, NSEQ, DIMM, DIMM, 0);
    tgemm<<<dim3(DIMM/128, NSEQ/128), 256>>>(tout, w_out + (long)DIMM*DIMM, out, NSEQ, DIMM, DIMM, 1);

    // 6) memories
    memories_kernel<<<(2*HEADS*WIDTH*HD)/256, 256>>>(qkv, out + (long)NSEQ*DIMM);

    // 7) state output path
    tgemm<<<dim3(DIMM/128, NST/128), 256>>>(scat, w_sout, so, NST, DIMM, 2*DIMM, 0);
    tgemm<<<dim3(DIMM/128, NST/128), 256>>>(so, w_gate, zb, NST, DIMM, DIMM, 0);
    newstates_kernel<<<(NST*DIMM)/256, 256>>>(zb, b_gate, beta, init_st,
            out + (long)NSEQ*DIMM + 2*HEADS*WIDTH*HD);
}

// round 8
// speedup vs baseline: 1.4216x; 1.0046x over previous
#include <cuda_runtime.h>
#include <math.h>

#define NSEQ  4096
#define DIMM  1024
#define HEADS 16
#define HD    64
#define WIDTH 512
#define NW    8
#define NST   512
#define KEYW  1024

// ---------------- scratch ----------------
__device__ float g_xn[NSEQ*DIMM];
__device__ float g_qkv[NSEQ*3*DIMM];
__device__ float g_q2s[NSEQ*DIMM];
__device__ float g_state_qkv[NST*3*DIMM];
__device__ float g_st[NST*DIMM];
__device__ float g_qfs_raw[NST*DIMM];

__device__ float g_qn_main[HEADS*NSEQ*HD];
__device__ float g_kn_main[HEADS*NSEQ*HD];
__device__ float g_qn_ts[HEADS*NSEQ*HD];
__device__ float g_kn_ts[HEADS*NST*HD];
__device__ float g_qn_ss[HEADS*NST*HD];
__device__ float g_kn_ss[HEADS*NST*HD];
__device__ float g_qn_fs[HEADS*NST*HD];
__device__ float g_kn_fs[HEADS*NST*HD];

__device__ float g_attn_out[NSEQ*DIMM];
__device__ float g_ts_out[NSEQ*DIMM];
__device__ float g_state_cat[NST*2*DIMM];
__device__ float g_so[NST*DIMM];
__device__ float g_z[NST*DIMM];

// ---------------- layernorm ----------------
__global__ void __launch_bounds__(256) ln_kernel(const float* __restrict__ x,
        const float* __restrict__ gamma, const float* __restrict__ pos,
        float* __restrict__ out)
{
    int row = blockIdx.x;
    const float* xr = x + (long)row*DIMM;
    float* orow = out + (long)row*DIMM;
    __shared__ float red[256];
    float s = 0.f, s2 = 0.f;
    for (int i = threadIdx.x; i < DIMM; i += 256) { float v = xr[i]; s += v; s2 += v*v; }
    red[threadIdx.x] = s; __syncthreads();
    for (int o = 128; o; o >>= 1) { if (threadIdx.x < o) red[threadIdx.x] += red[threadIdx.x+o]; __syncthreads(); }
    float mu = red[0] * (1.f/DIMM);
    __syncthreads();
    red[threadIdx.x] = s2; __syncthreads();
    for (int o = 128; o; o >>= 1) { if (threadIdx.x < o) red[threadIdx.x] += red[threadIdx.x+o]; __syncthreads(); }
    float var = red[0] * (1.f/DIMM) - mu*mu;
    float inv = rsqrtf(var + 1e-5f);
    for (int i = threadIdx.x; i < DIMM; i += 256) {
        float v = (xr[i]-mu)*inv*gamma[i];
        if (pos) v += pos[(long)row*DIMM + i];
        orow[i] = v;
    }
}

// ---------------- TF32 helpers ----------------
__device__ __forceinline__ unsigned f2tf32(float f)
{
    unsigned r;
    asm("cvt.rna.tf32.f32 %0, %1;" : "=r"(r) : "f"(f));
    return r;
}

__device__ __forceinline__ void mma_tf32(float c[4], const unsigned a[4], const unsigned b[2])
{
    asm volatile(
        "mma.sync.aligned.m16n8k8.row.col.f32.tf32.tf32.f32 "
        "{%0,%1,%2,%3}, {%4,%5,%6,%7}, {%8,%9}, {%0,%1,%2,%3};"
        : "+f"(c[0]), "+f"(c[1]), "+f"(c[2]), "+f"(c[3])
        : "r"(a[0]), "r"(a[1]), "r"(a[2]), "r"(a[3]), "r"(b[0]), "r"(b[1]));
}

// ---------------- TF32 tensor-core GEMM ----------------
__global__ void __launch_bounds__(256) tgemm(const float* __restrict__ A,
        const float* __restrict__ B, float* __restrict__ C,
        int M, int N, int K, int accum)
{
    __shared__ unsigned As[2][16][132];
    __shared__ unsigned Bs[2][16][132];

    int tid = threadIdx.x;
    int warp = tid >> 5, lane = tid & 31;
    int wy = warp >> 1, wx = warp & 1;
    int g = lane >> 2, t4 = lane & 3;
    int m0 = blockIdx.y*128, n0 = blockIdx.x*128;

    int arow = tid >> 2;
    int acol = (tid & 3) * 4;
    int bkrow = tid >> 5;
    int bcol = lane * 4;

    const float* Abase = A + (long)(m0 + arow)*K + acol;
    const float* Bbase = B + (long)bkrow*N + n0 + bcol;

    float acc[2][8][4];
    #pragma unroll
    for (int mi = 0; mi < 2; mi++)
        #pragma unroll
        for (int nj = 0; nj < 8; nj++)
            #pragma unroll
            for (int c = 0; c < 4; c++) acc[mi][nj][c] = 0.f;

    float4 ra0, ra1, rb0, rb1;

    auto ldg = [&](int kt) {
        ra0 = *(const float4*)(Abase + kt*16);
        ra1 = *(const float4*)(Abase + kt*16 + (long)64*K);
        rb0 = *(const float4*)(Bbase + (long)kt*16*N);
        rb1 = *(const float4*)(Bbase + (long)(kt*16+8)*N);
    };
    auto sts = [&](int buf) {
        As[buf][acol+0][arow] = f2tf32(ra0.x);
        As[buf][acol+1][arow] = f2tf32(ra0.y);
        As[buf][acol+2][arow] = f2tf32(ra0.z);
        As[buf][acol+3][arow] = f2tf32(ra0.w);
        As[buf][acol+0][arow+64] = f2tf32(ra1.x);
        As[buf][acol+1][arow+64] = f2tf32(ra1.y);
        As[buf][acol+2][arow+64] = f2tf32(ra1.z);
        As[buf][acol+3][arow+64] = f2tf32(ra1.w);
        Bs[buf][bkrow][bcol+0] = f2tf32(rb0.x);
        Bs[buf][bkrow][bcol+1] = f2tf32(rb0.y);
        Bs[buf][bkrow][bcol+2] = f2tf32(rb0.z);
        Bs[buf][bkrow][bcol+3] = f2tf32(rb0.w);
        Bs[buf][bkrow+8][bcol+0] = f2tf32(rb1.x);
        Bs[buf][bkrow+8][bcol+1] = f2tf32(rb1.y);
        Bs[buf][bkrow+8][bcol+2] = f2tf32(rb1.z);
        Bs[buf][bkrow+8][bcol+3] = f2tf32(rb1.w);
    };

    ldg(0); sts(0);
    __syncthreads();

    int nkt = K >> 4;
    for (int kt = 0; kt < nkt; kt++) {
        int buf = kt & 1;
        if (kt + 1 < nkt) ldg(kt + 1);

        #pragma unroll
        for (int ks = 0; ks < 2; ks++) {
            int kk = ks*8;
            unsigned af[2][4], bf[8][2];
            #pragma unroll
            for (int mi = 0; mi < 2; mi++) {
                int mr = wy*32 + mi*16 + g;
                af[mi][0] = As[buf][kk + t4][mr];
                af[mi][1] = As[buf][kk + t4][mr + 8];
                af[mi][2] = As[buf][kk + t4 + 4][mr];
                af[mi][3] = As[buf][kk + t4 + 4][mr + 8];
            }
            #pragma unroll
            for (int nj = 0; nj < 8; nj++) {
                int nc = wx*64 + nj*8 + g;
                bf[nj][0] = Bs[buf][kk + t4][nc];
                bf[nj][1] = Bs[buf][kk + t4 + 4][nc];
            }
            #pragma unroll
            for (int mi = 0; mi < 2; mi++)
                #pragma unroll
                for (int nj = 0; nj < 8; nj++)
                    mma_tf32(acc[mi][nj], af[mi], bf[nj]);
        }

        if (kt + 1 < nkt) sts(buf ^ 1);
        __syncthreads();
    }

    #pragma unroll
    for (int mi = 0; mi < 2; mi++) {
        #pragma unroll
        for (int nj = 0; nj < 8; nj++) {
            int row = m0 + wy*32 + mi*16 + g;
            int col = n0 + wx*64 + nj*8 + t4*2;
            float* p0 = &C[(long)row*N + col];
            float* p1 = &C[(long)(row+8)*N + col];
            float2 v0 = make_float2(acc[mi][nj][0], acc[mi][nj][1]);
            float2 v1 = make_float2(acc[mi][nj][2], acc[mi][nj][3]);
            if (accum) {
                float2 o0 = *(float2*)p0, o1 = *(float2*)p1;
                v0.x += o0.x; v0.y += o0.y; v1.x += o1.x; v1.y += o1.y;
            }
            *(float2*)p0 = v0;
            *(float2*)p1 = v1;
        }
    }
}

// ---------------- l2norm + scale, head-major ----------------
__global__ void norm_heads(const float* __restrict__ src, int srcStride, int colOff,
        int rowOff, const float* __restrict__ scale, float* __restrict__ dst, int nrows)
{
    int row = blockIdx.x, h = blockIdx.y, d = threadIdx.x;
    float v = src[(long)(rowOff+row)*srcStride + colOff + h*HD + d];
    float s = v*v;
    #pragma unroll
    for (int o = 16; o; o >>= 1) s += __shfl_xor_sync(0xffffffffu, s, o);
    __shared__ float sh[2];
    if ((d & 31) == 0) sh[d>>5] = s;
    __syncthreads();
    float inv = 1.f / fmaxf(sqrtf(sh[0]+sh[1]), 1e-12f);
    dst[((long)h*nrows + row)*HD + d] = v*inv*scale[d];
}

// ---------------- fused flash attention: 128-row q tiles, 64-key chunks ----------------
// SMEM: Qs [64 d][132], Ks [64 d][68], Vs [64 key][68], Ps [64 key][132]
#define QP 132
#define KP 68
#define FLASH_SMEM ((2*64*QP + 2*64*KP)*4)

__global__ void __launch_bounds__(256, 2) flash128(
        const float* __restrict__ Q, int qHeadRows,
        const float* __restrict__ Kh, int kHeadRows,
        const float* __restrict__ Vall, long vstride, int vColHeadMul, int vColAdd,
        int vRowExtra,
        const float* __restrict__ bias,
        float* __restrict__ Out, long ostride, int oColMul, int oColAdd,
        int L, int nwin)
{
    extern __shared__ float sm[];
    float* Qs = sm;                    // [64][QP]  (d, row)
    float* Ks = sm + 64*QP;            // [64][KP]  (d, key)
    float* Vs = sm + 64*QP + 64*KP;    // [64][KP]  (key, d)
    float* Ps = sm + 64*QP + 2*64*KP;  // [64][QP]  (key, row)

    int tid = threadIdx.x;
    int tx = tid & 15, ty = tid >> 4;

    int z = blockIdx.y;
    int h = z / nwin, w = z - h*nwin;
    int winw = qHeadRows / nwin;
    int i0 = blockIdx.x*128;              // local row within window
    int qrow0 = w*winw + i0;
    int kOff = (nwin > 1) ? (w-1)*winw : 0;

    const float* Qblk = Q + ((long)h*qHeadRows + qrow0)*64;
    const float* Kbase = Kh + (long)h*kHeadRows*64;
    const float* Vbase = Vall + vColHeadMul*h + vColAdd;
    const float* biasH = bias ? bias + (long)h*WIDTH*KEYW : nullptr;

    // load Q tile (128x64) transposed into Qs[d][row] — once per CTA
    #pragma unroll
    for (int t = 0; t < 8; t++) {
        int e = tid + t*256;
        int r = e >> 4, c4 = (e & 15)*4;
        float4 v = *(const float4*)&Qblk[(long)r*64 + c4];
        Qs[(c4+0)*QP + r] = v.x;
        Qs[(c4+1)*QP + r] = v.y;
        Qs[(c4+2)*QP + r] = v.z;
        Qs[(c4+3)*QP + r] = v.w;
    }

    float m[8], l[8], acc[8][4];
    #pragma unroll
    for (int i = 0; i < 8; i++) {
        m[i] = -3.402823466e38f; l[i] = 0.f;
        #pragma unroll
        for (int j = 0; j < 4; j++) acc[i][j] = 0.f;
    }
    __syncthreads();

    int Lq = biasH ? (i0 + 640) : L;    // rows i0..i0+127 need keys <= i0+127+512
    if (Lq > L) Lq = L;

    for (int c0 = 0; c0 < Lq; c0 += 64) {
        // load K chunk transposed (Ks[d][key]) and V chunk (Vs[key][d])
        #pragma unroll
        for (int t = 0; t < 4; t++) {
            int e = tid + t*256;
            int r = e >> 4, c4 = (e & 15)*4;
            int kr = kOff + c0 + r;
            float4 kv = make_float4(0.f,0.f,0.f,0.f), vv = kv;
            if (kr >= 0) {
                kv = *(const float4*)&Kbase[(long)kr*64 + c4];
                vv = *(const float4*)&Vbase[(long)(kr + vRowExtra)*vstride + c4];
            }
            Ks[(c4+0)*KP + r] = kv.x;
            Ks[(c4+1)*KP + r] = kv.y;
            Ks[(c4+2)*KP + r] = kv.z;
            Ks[(c4+3)*KP + r] = kv.w;
            *(float4*)&Vs[r*KP + c4] = vv;
        }
        __syncthreads();

        // ---- S = Q @ K^T ----
        float s[8][4];
        #pragma unroll
        for (int i = 0; i < 8; i++)
            #pragma unroll
            for (int j = 0; j < 4; j++) s[i][j] = 0.f;

        #pragma unroll 16
        for (int kk = 0; kk < 64; kk++) {
            float a[8], b[4];
            *(float4*)(a)   = *(const float4*)&Qs[kk*QP + ty*8];
            *(float4*)(a+4) = *(const float4*)&Qs[kk*QP + ty*8 + 4];
            *(float4*)(b)   = *(const float4*)&Ks[kk*KP + tx*4];
            #pragma unroll
            for (int i = 0; i < 8; i++)
                #pragma unroll
                for (int j = 0; j < 4; j++)
                    s[i][j] += a[i]*b[j];
        }

        // ---- scale + bias + mask ----
        #pragma unroll
        for (int i = 0; i < 8; i++) {
            int irow = i0 + ty*8 + i;
            #pragma unroll
            for (int j = 0; j < 4; j++) s[i][j] *= 8.f;
            if (biasH) {
                int j0 = c0 + tx*4;
                float4 bv = *(const float4*)&biasH[(long)irow*KEYW + j0];
                s[i][0] += bv.x; s[i][1] += bv.y; s[i][2] += bv.z; s[i][3] += bv.w;
                if (j0     > irow + 512) s[i][0] = -3.402823466e38f;
                if (j0 + 1 > irow + 512) s[i][1] = -3.402823466e38f;
                if (j0 + 2 > irow + 512) s[i][2] = -3.402823466e38f;
                if (j0 + 3 > irow + 512) s[i][3] = -3.402823466e38f;
            }
        }

        // ---- online softmax + write P transposed [key][row] ----
        #pragma unroll
        for (int i = 0; i < 8; i++) {
            float cm = fmaxf(fmaxf(s[i][0], s[i][1]), fmaxf(s[i][2], s[i][3]));
            #pragma unroll
            for (int o = 8; o; o >>= 1) cm = fmaxf(cm, __shfl_xor_sync(0xffffffffu, cm, o));
            float mnew = fmaxf(m[i], cm);
            float corr = __expf(m[i] - mnew);
            l[i] *= corr;
            #pragma unroll
            for (int j = 0; j < 4; j++) acc[i][j] *= corr;
            float rs = 0.f;
            #pragma unroll
            for (int j = 0; j < 4; j++) {
                float p = __expf(s[i][j] - mnew);
                s[i][j] = p;
                rs += p;
            }
            #pragma unroll
            for (int o = 8; o; o >>= 1) rs += __shfl_xor_sync(0xffffffffu, rs, o);
            l[i] += rs;
            m[i] = mnew;
        }
        // store P: Ps[key = tx*4+j][row = ty*8 + 0..7] as two float4 per j
        #pragma unroll
        for (int j = 0; j < 4; j++) {
            float4 lo = make_float4(s[0][j], s[1][j], s[2][j], s[3][j]);
            float4 hi = make_float4(s[4][j], s[5][j], s[6][j], s[7][j]);
            *(float4*)&Ps[(tx*4+j)*QP + ty*8]     = lo;
            *(float4*)&Ps[(tx*4+j)*QP + ty*8 + 4] = hi;
        }
        __syncthreads();

        // ---- acc += P @ V ----
        #pragma unroll 16
        for (int kk = 0; kk < 64; kk++) {
            float a[8], b[4];
            *(float4*)(a)   = *(const float4*)&Ps[kk*QP + ty*8];
            *(float4*)(a+4) = *(const float4*)&Ps[kk*QP + ty*8 + 4];
            *(float4*)(b)   = *(const float4*)&Vs[kk*KP + tx*4];
            #pragma unroll
            for (int i = 0; i < 8; i++)
                #pragma unroll
                for (int j = 0; j < 4; j++)
                    acc[i][j] += a[i]*b[j];
        }
        __syncthreads();
    }

    // epilogue
    #pragma unroll
    for (int i = 0; i < 8; i++) {
        float inv = 1.f / l[i];
        long orow = (long)(qrow0 + ty*8 + i)*ostride + h*oColMul + oColAdd + tx*4;
        float4 v = make_float4(acc[i][0]*inv, acc[i][1]*inv, acc[i][2]*inv, acc[i][3]*inv);
        *(float4*)&Out[orow] = v;
    }
}

// ---------------- memories copy ----------------
__global__ void memories_kernel(const float* __restrict__ qkv, float* __restrict__ out)
{
    int idx = blockIdx.x*256 + threadIdx.x;
    if (idx >= 2*HEADS*WIDTH*HD) return;
    int d = idx & 63;
    int i = (idx >> 6) & 511;
    int h = (idx >> 15) & 15;
    int s = idx >> 19;
    out[idx] = qkv[(long)(3584+i)*3072 + (s ? 2048 : 1024) + h*HD + d];
}

// ---------------- new_states ----------------
__global__ void newstates_kernel(const float* __restrict__ gz, const float* __restrict__ bg,
        const float* __restrict__ beta, const float* __restrict__ init_state,
        float* __restrict__ out)
{
    int idx = blockIdx.x*256 + threadIdx.x;
    if (idx >= NST*DIMM) return;
    int c = idx & (DIMM-1);
    float sig = 1.f/(1.f+expf(-beta[c]));
    float z = gz[idx] + bg[c];
    out[idx] = sig*z + (1.f-sig)*init_state[idx];
}

// ---------------- host launch ----------------
static float* symaddr(const void* s)
{
    void* p = nullptr;
    cudaGetSymbolAddress(&p, s);
    return (float*)p;
}

extern "C" void kernel_launch(void* const* d_in, const int* in_sizes, int n_in,
                              void* d_out, int out_size)
{
    const float* x       = (const float*)d_in[0];
    const float* bias    = (const float*)d_in[1];
    const float* gamma   = (const float*)d_in[2];
    const float* w_qkv   = (const float*)d_in[3];
    const float* q_scale = (const float*)d_in[4];
    const float* k_scale = (const float*)d_in[5];
    const float* w_out   = (const float*)d_in[6];
    const float* s_gamma = (const float*)d_in[7];
    const float* w_q2s   = (const float*)d_in[8];
    const float* w_qfs   = (const float*)d_in[9];
    const float* w_sqkv  = (const float*)d_in[10];
    const float* init_st = (const float*)d_in[11];
    const float* pos_ids = (const float*)d_in[12];
    const float* w_sout  = (const float*)d_in[13];
    const float* ts_q    = (const float*)d_in[14];
    const float* ts_k    = (const float*)d_in[15];
    const float* ss_q    = (const float*)d_in[16];
    const float* ss_k    = (const float*)d_in[17];
    const float* fs_q    = (const float*)d_in[18];
    const float* fs_k    = (const float*)d_in[19];
    const float* w_gate  = (const float*)d_in[20];
    const float* b_gate  = (const float*)d_in[21];
    const float* beta    = (const float*)d_in[22];
    float* out = (float*)d_out;

    float* xn   = symaddr(g_xn);
    float* qkv  = symaddr(g_qkv);
    float* q2s  = symaddr(g_q2s);
    float* sqkv = symaddr(g_state_qkv);
    float* st   = symaddr(g_st);
    float* qfsr = symaddr(g_qfs_raw);
    float* qnm  = symaddr(g_qn_main);
    float* knm  = symaddr(g_kn_main);
    float* qnts = symaddr(g_qn_ts);
    float* knts = symaddr(g_kn_ts);
    float* qnss = symaddr(g_qn_ss);
    float* knss = symaddr(g_kn_ss);
    float* qnfs = symaddr(g_qn_fs);
    float* knfs = symaddr(g_kn_fs);
    float* aout = symaddr(g_attn_out);
    float* tout = symaddr(g_ts_out);
    float* scat = symaddr(g_state_cat);
    float* so   = symaddr(g_so);
    float* zb   = symaddr(g_z);

    cudaFuncSetAttribute(flash128, cudaFuncAttributeMaxDynamicSharedMemorySize, FLASH_SMEM);

    // 1) layernorms
    ln_kernel<<<NSEQ, 256>>>(x, gamma, nullptr, xn);
    ln_kernel<<<NST, 256>>>(init_st, s_gamma, pos_ids, st);

    // 2) projections (TF32 tensor cores)
    tgemm<<<dim3(3072/128, NSEQ/128), 256>>>(xn, w_qkv, qkv, NSEQ, 3072, DIMM, 0);
    tgemm<<<dim3(DIMM/128, NSEQ/128), 256>>>(xn, w_q2s, q2s, NSEQ, DIMM, DIMM, 0);
    tgemm<<<dim3(3072/128, NST/128), 256>>>(init_st, w_sqkv, sqkv, NST, 3072, DIMM, 0);
    tgemm<<<dim3(DIMM/128, NST/128), 256>>>(st, w_qfs, qfsr, NST, DIMM, DIMM, 0);

    // 3) l2norm + scale, head-major
    norm_heads<<<dim3(NSEQ, HEADS), 64>>>(qkv, 3072, 0,    0,    q_scale, qnm,  NSEQ);
    norm_heads<<<dim3(NSEQ, HEADS), 64>>>(qkv, 3072, 1024, 0,    k_scale, knm,  NSEQ);
    norm_heads<<<dim3(NSEQ, HEADS), 64>>>(q2s, 1024, 0,    0,    ts_q,    qnts, NSEQ);
    norm_heads<<<dim3(NST,  HEADS), 64>>>(sqkv, 3072, 1024, 0,   ts_k,    knts, NST);
    norm_heads<<<dim3(NST,  HEADS), 64>>>(sqkv, 3072, 0,    0,   ss_q,    qnss, NST);
    norm_heads<<<dim3(NST,  HEADS), 64>>>(sqkv, 3072, 1024, 0,   ss_k,    knss, NST);
    norm_heads<<<dim3(NST,  HEADS), 64>>>(qfsr, 1024, 0,    0,   fs_q,    qnfs, NST);
    norm_heads<<<dim3(NST,  HEADS), 64>>>(qkv,  3072, 1024, 3584, fs_k,   knfs, NST);

    // 4) fused attentions (scalar flash, 128-row tiles, causal chunk skip)
    flash128<<<dim3(WIDTH/128, HEADS*NW), 256, FLASH_SMEM>>>(
        qnm, NSEQ, knm, NSEQ, qkv, 3072, HD, 2048, 0, bias,
        aout, DIMM, HD, 0, KEYW, NW);
    flash128<<<dim3(NSEQ/128, HEADS), 256, FLASH_SMEM>>>(
        qnts, NSEQ, knts, NST, sqkv, 3072, HD, 2048, 0, nullptr,
        tout, DIMM, HD, 0, NST, 1);
    flash128<<<dim3(NST/128, HEADS), 256, FLASH_SMEM>>>(
        qnss, NST, knss, NST, sqkv, 3072, HD, 2048, 0, nullptr,
        scat, 2*DIMM, 2*HD, 0, NST, 1);
    flash128<<<dim3(NST/128, HEADS), 256, FLASH_SMEM>>>(
        qnfs, NST, knfs, NST, qkv, 3072, HD, 2048, 3584, nullptr,
        scat, 2*DIMM, 2*HD, HD, NST, 1);

    // 5) output projections
    tgemm<<<dim3(DIMM/128, NSEQ/128), 256>>>(aout, w_out, out, NSEQ, DIMM, DIMM, 0);
    tgemm<<<dim3(DIMM/128, NSEQ/128), 256>>>(tout, w_out + (long)DIMM*DIMM, out, NSEQ, DIMM, DIMM, 1);

    // 6) memories
    memories_kernel<<<(2*HEADS*WIDTH*HD)/256, 256>>>(qkv, out + (long)NSEQ*DIMM);

    // 7) state output path
    tgemm<<<dim3(DIMM/128, NST/128), 256>>>(scat, w_sout, so, NST, DIMM, 2*DIMM, 0);
    tgemm<<<dim3(DIMM/128, NST/128), 256>>>(so, w_gate, zb, NST, DIMM, DIMM, 0);
    newstates_kernel<<<(NST*DIMM)/256, 256>>>(zb, b_gate, beta, init_st,
            out + (long)NSEQ*DIMM + 2*HEADS*WIDTH*HD);
}

// round 9
// speedup vs baseline: 1.5036x; 1.0576x over previous
#include <cuda_runtime.h>
#include <math.h>

#define NSEQ  4096
#define DIMM  1024
#define HEADS 16
#define HD    64
#define WIDTH 512
#define NW    8
#define NST   512
#define KEYW  1024

// ---------------- scratch ----------------
__device__ float g_xn[NSEQ*DIMM];
__device__ float g_qkv[NSEQ*3*DIMM];
__device__ float g_q2s[NSEQ*DIMM];
__device__ float g_state_qkv[NST*3*DIMM];
__device__ float g_st[NST*DIMM];
__device__ float g_qfs_raw[NST*DIMM];

__device__ float g_qn_main[HEADS*NSEQ*HD];
__device__ float g_kn_main[HEADS*NSEQ*HD];
__device__ float g_qn_ts[HEADS*NSEQ*HD];
__device__ float g_kn_ts[HEADS*NST*HD];
__device__ float g_qn_ss[HEADS*NST*HD];
__device__ float g_kn_ss[HEADS*NST*HD];
__device__ float g_qn_fs[HEADS*NST*HD];
__device__ float g_kn_fs[HEADS*NST*HD];

__device__ float g_attn_out[NSEQ*DIMM];
__device__ float g_ts_out[NSEQ*DIMM];
__device__ float g_state_cat[NST*2*DIMM];
__device__ float g_so[NST*DIMM];
__device__ float g_z[NST*DIMM];

// ---------------- layernorm ----------------
__global__ void __launch_bounds__(256) ln_kernel(const float* __restrict__ x,
        const float* __restrict__ gamma, const float* __restrict__ pos,
        float* __restrict__ out)
{
    int row = blockIdx.x;
    const float* xr = x + (long)row*DIMM;
    float* orow = out + (long)row*DIMM;
    __shared__ float red[256];
    float s = 0.f, s2 = 0.f;
    for (int i = threadIdx.x; i < DIMM; i += 256) { float v = xr[i]; s += v; s2 += v*v; }
    red[threadIdx.x] = s; __syncthreads();
    for (int o = 128; o; o >>= 1) { if (threadIdx.x < o) red[threadIdx.x] += red[threadIdx.x+o]; __syncthreads(); }
    float mu = red[0] * (1.f/DIMM);
    __syncthreads();
    red[threadIdx.x] = s2; __syncthreads();
    for (int o = 128; o; o >>= 1) { if (threadIdx.x < o) red[threadIdx.x] += red[threadIdx.x+o]; __syncthreads(); }
    float var = red[0] * (1.f/DIMM) - mu*mu;
    float inv = rsqrtf(var + 1e-5f);
    for (int i = threadIdx.x; i < DIMM; i += 256) {
        float v = (xr[i]-mu)*inv*gamma[i];
        if (pos) v += pos[(long)row*DIMM + i];
        orow[i] = v;
    }
}

// ---------------- TF32 helpers ----------------
__device__ __forceinline__ unsigned f2tf32(float f)
{
    unsigned r;
    asm("cvt.rna.tf32.f32 %0, %1;" : "=r"(r) : "f"(f));
    return r;
}

__device__ __forceinline__ void mma_tf32(float c[4], const unsigned a[4], const unsigned b[2])
{
    asm volatile(
        "mma.sync.aligned.m16n8k8.row.col.f32.tf32.tf32.f32 "
        "{%0,%1,%2,%3}, {%4,%5,%6,%7}, {%8,%9}, {%0,%1,%2,%3};"
        : "+f"(c[0]), "+f"(c[1]), "+f"(c[2]), "+f"(c[3])
        : "r"(a[0]), "r"(a[1]), "r"(a[2]), "r"(a[3]), "r"(b[0]), "r"(b[1]));
}

// ---------------- TF32 tensor-core GEMM ----------------
__global__ void __launch_bounds__(256) tgemm(const float* __restrict__ A,
        const float* __restrict__ B, float* __restrict__ C,
        int M, int N, int K, int accum)
{
    __shared__ unsigned As[2][16][132];
    __shared__ unsigned Bs[2][16][132];

    int tid = threadIdx.x;
    int warp = tid >> 5, lane = tid & 31;
    int wy = warp >> 1, wx = warp & 1;
    int g = lane >> 2, t4 = lane & 3;
    int m0 = blockIdx.y*128, n0 = blockIdx.x*128;

    int arow = tid >> 2;
    int acol = (tid & 3) * 4;
    int bkrow = tid >> 5;
    int bcol = lane * 4;

    const float* Abase = A + (long)(m0 + arow)*K + acol;
    const float* Bbase = B + (long)bkrow*N + n0 + bcol;

    float acc[2][8][4];
    #pragma unroll
    for (int mi = 0; mi < 2; mi++)
        #pragma unroll
        for (int nj = 0; nj < 8; nj++)
            #pragma unroll
            for (int c = 0; c < 4; c++) acc[mi][nj][c] = 0.f;

    float4 ra0, ra1, rb0, rb1;

    auto ldg = [&](int kt) {
        ra0 = *(const float4*)(Abase + kt*16);
        ra1 = *(const float4*)(Abase + kt*16 + (long)64*K);
        rb0 = *(const float4*)(Bbase + (long)kt*16*N);
        rb1 = *(const float4*)(Bbase + (long)(kt*16+8)*N);
    };
    auto sts = [&](int buf) {
        As[buf][acol+0][arow] = f2tf32(ra0.x);
        As[buf][acol+1][arow] = f2tf32(ra0.y);
        As[buf][acol+2][arow] = f2tf32(ra0.z);
        As[buf][acol+3][arow] = f2tf32(ra0.w);
        As[buf][acol+0][arow+64] = f2tf32(ra1.x);
        As[buf][acol+1][arow+64] = f2tf32(ra1.y);
        As[buf][acol+2][arow+64] = f2tf32(ra1.z);
        As[buf][acol+3][arow+64] = f2tf32(ra1.w);
        Bs[buf][bkrow][bcol+0] = f2tf32(rb0.x);
        Bs[buf][bkrow][bcol+1] = f2tf32(rb0.y);
        Bs[buf][bkrow][bcol+2] = f2tf32(rb0.z);
        Bs[buf][bkrow][bcol+3] = f2tf32(rb0.w);
        Bs[buf][bkrow+8][bcol+0] = f2tf32(rb1.x);
        Bs[buf][bkrow+8][bcol+1] = f2tf32(rb1.y);
        Bs[buf][bkrow+8][bcol+2] = f2tf32(rb1.z);
        Bs[buf][bkrow+8][bcol+3] = f2tf32(rb1.w);
    };

    ldg(0); sts(0);
    __syncthreads();

    int nkt = K >> 4;
    for (int kt = 0; kt < nkt; kt++) {
        int buf = kt & 1;
        if (kt + 1 < nkt) ldg(kt + 1);

        #pragma unroll
        for (int ks = 0; ks < 2; ks++) {
            int kk = ks*8;
            unsigned af[2][4], bf[8][2];
            #pragma unroll
            for (int mi = 0; mi < 2; mi++) {
                int mr = wy*32 + mi*16 + g;
                af[mi][0] = As[buf][kk + t4][mr];
                af[mi][1] = As[buf][kk + t4][mr + 8];
                af[mi][2] = As[buf][kk + t4 + 4][mr];
                af[mi][3] = As[buf][kk + t4 + 4][mr + 8];
            }
            #pragma unroll
            for (int nj = 0; nj < 8; nj++) {
                int nc = wx*64 + nj*8 + g;
                bf[nj][0] = Bs[buf][kk + t4][nc];
                bf[nj][1] = Bs[buf][kk + t4 + 4][nc];
            }
            #pragma unroll
            for (int mi = 0; mi < 2; mi++)
                #pragma unroll
                for (int nj = 0; nj < 8; nj++)
                    mma_tf32(acc[mi][nj], af[mi], bf[nj]);
        }

        if (kt + 1 < nkt) sts(buf ^ 1);
        __syncthreads();
    }

    #pragma unroll
    for (int mi = 0; mi < 2; mi++) {
        #pragma unroll
        for (int nj = 0; nj < 8; nj++) {
            int row = m0 + wy*32 + mi*16 + g;
            int col = n0 + wx*64 + nj*8 + t4*2;
            float* p0 = &C[(long)row*N + col];
            float* p1 = &C[(long)(row+8)*N + col];
            float2 v0 = make_float2(acc[mi][nj][0], acc[mi][nj][1]);
            float2 v1 = make_float2(acc[mi][nj][2], acc[mi][nj][3]);
            if (accum) {
                float2 o0 = *(float2*)p0, o1 = *(float2*)p1;
                v0.x += o0.x; v0.y += o0.y; v1.x += o1.x; v1.y += o1.y;
            }
            *(float2*)p0 = v0;
            *(float2*)p1 = v1;
        }
    }
}

// ---------------- l2norm + scale, head-major ----------------
__global__ void norm_heads(const float* __restrict__ src, int srcStride, int colOff,
        int rowOff, const float* __restrict__ scale, float* __restrict__ dst, int nrows)
{
    int row = blockIdx.x, h = blockIdx.y, d = threadIdx.x;
    float v = src[(long)(rowOff+row)*srcStride + colOff + h*HD + d];
    float s = v*v;
    #pragma unroll
    for (int o = 16; o; o >>= 1) s += __shfl_xor_sync(0xffffffffu, s, o);
    __shared__ float sh[2];
    if ((d & 31) == 0) sh[d>>5] = s;
    __syncthreads();
    float inv = 1.f / fmaxf(sqrtf(sh[0]+sh[1]), 1e-12f);
    dst[((long)h*nrows + row)*HD + d] = v*inv*scale[d];
}

// ---------------- flash attention: QK^T compensated tf32, PV single tf32 ----------------
#define FPAD 68
#define TILEU (64*FPAD)
#define FLASH_SMEM (6*TILEU*4 + 256*4)

__global__ void __launch_bounds__(256, 2) flashmma(
        const float* __restrict__ Q, int qHeadRows,
        const float* __restrict__ Kh, int kHeadRows,
        const float* __restrict__ Vall, long vstride, int vColHeadMul, int vColAdd,
        int vRowExtra,
        const float* __restrict__ bias,
        float* __restrict__ Out, long ostride, int oColMul, int oColAdd,
        int L, int nwin)
{
    extern __shared__ unsigned usm[];
    unsigned* QHI = usm;
    unsigned* QLO = usm + TILEU;
    unsigned* KHI = usm + 2*TILEU;
    unsigned* KLO = usm + 3*TILEU;
    unsigned* VS  = usm + 4*TILEU;
    unsigned* PT  = usm + 5*TILEU;
    float* SMAX = (float*)(usm + 6*TILEU);   // [64][2]
    float* SSUM = SMAX + 128;                // [64][2]

    int tid = threadIdx.x;
    int warp = tid >> 5, lane = tid & 31;
    int wy = warp >> 1, wx = warp & 1;
    int g = lane >> 2, t4 = lane & 3;

    int z = blockIdx.y;
    int h = z / nwin, w = z - h*nwin;
    int winw = qHeadRows / nwin;
    int i0 = blockIdx.x*64;
    int qrow0 = w*winw + i0;
    int kOff = (nwin > 1) ? (w-1)*winw : 0;

    const float* Qblk = Q + ((long)h*qHeadRows + qrow0)*64;
    const float* Kbase = Kh + (long)h*kHeadRows*64;
    const float* Vbase = Vall + vColHeadMul*h + vColAdd;
    const float* biasH = bias ? bias + (long)h*WIDTH*KEYW : nullptr;

    // load Q, split hi/lo, store [d][row]
    #pragma unroll
    for (int t = 0; t < 16; t++) {
        int e = tid + t*256;
        int r = e >> 6, c = e & 63;
        float v = Qblk[(long)r*64 + c];
        unsigned hi = f2tf32(v);
        QHI[c*FPAD + r] = hi;
        QLO[c*FPAD + r] = f2tf32(v - __uint_as_float(hi));
    }

    int mr = wy*16 + g;
    float m0r = -3.402823466e38f, m1r = -3.402823466e38f;
    float l0 = 0.f, l1 = 0.f;
    float acc[4][4];
    #pragma unroll
    for (int nj = 0; nj < 4; nj++)
        #pragma unroll
        for (int c = 0; c < 4; c++) acc[nj][c] = 0.f;

    int Lq = biasH ? (i0 + 576) : L;
    if (Lq > L) Lq = L;

    for (int c0 = 0; c0 < Lq; c0 += 64) {
        // load + split K [d][key]; V single [key][d]
        #pragma unroll
        for (int t = 0; t < 16; t++) {
            int e = tid + t*256;
            int r = e >> 6, cc = e & 63;
            int kr = kOff + c0 + r;
            float kv = (kr >= 0) ? Kbase[(long)kr*64 + cc] : 0.f;
            float vv = (kr >= 0) ? Vbase[(long)(kr + vRowExtra)*vstride + cc] : 0.f;
            unsigned khi = f2tf32(kv);
            KHI[cc*FPAD + r] = khi;
            KLO[cc*FPAD + r] = f2tf32(kv - __uint_as_float(khi));
            VS[r*FPAD + cc] = f2tf32(vv);
        }
        __syncthreads();

        // ---- S = Q @ K^T (compensated) ----
        float sf[4][4];
        #pragma unroll
        for (int nj = 0; nj < 4; nj++)
            #pragma unroll
            for (int c = 0; c < 4; c++) sf[nj][c] = 0.f;

        #pragma unroll
        for (int kk = 0; kk < 64; kk += 8) {
            unsigned ahi[4], alo[4];
            ahi[0] = QHI[(kk+t4)*FPAD + mr];
            ahi[1] = QHI[(kk+t4)*FPAD + mr + 8];
            ahi[2] = QHI[(kk+t4+4)*FPAD + mr];
            ahi[3] = QHI[(kk+t4+4)*FPAD + mr + 8];
            alo[0] = QLO[(kk+t4)*FPAD + mr];
            alo[1] = QLO[(kk+t4)*FPAD + mr + 8];
            alo[2] = QLO[(kk+t4+4)*FPAD + mr];
            alo[3] = QLO[(kk+t4+4)*FPAD + mr + 8];
            #pragma unroll
            for (int nj = 0; nj < 4; nj++) {
                int nc = wx*32 + nj*8 + g;
                unsigned bhi[2] = { KHI[(kk+t4)*FPAD + nc], KHI[(kk+t4+4)*FPAD + nc] };
                unsigned blo[2] = { KLO[(kk+t4)*FPAD + nc], KLO[(kk+t4+4)*FPAD + nc] };
                mma_tf32(sf[nj], ahi, bhi);
                mma_tf32(sf[nj], alo, bhi);
                mma_tf32(sf[nj], ahi, blo);
            }
        }

        // ---- scale + bias + mask ----
        int ir0 = i0 + mr, ir1 = ir0 + 8;
        #pragma unroll
        for (int nj = 0; nj < 4; nj++) {
            int j0 = c0 + wx*32 + nj*8 + 2*t4;
            #pragma unroll
            for (int c = 0; c < 4; c++) sf[nj][c] *= 8.f;
            if (biasH) {
                float2 b0 = *(const float2*)&biasH[(long)ir0*KEYW + j0];
                float2 b1 = *(const float2*)&biasH[(long)ir1*KEYW + j0];
                sf[nj][0] += b0.x; sf[nj][1] += b0.y;
                sf[nj][2] += b1.x; sf[nj][3] += b1.y;
                if (j0     > ir0 + 512) sf[nj][0] = -3.402823466e38f;
                if (j0 + 1 > ir0 + 512) sf[nj][1] = -3.402823466e38f;
                if (j0     > ir1 + 512) sf[nj][2] = -3.402823466e38f;
                if (j0 + 1 > ir1 + 512) sf[nj][3] = -3.402823466e38f;
            }
        }

        // ---- row max ----
        float pm0 = -3.402823466e38f, pm1 = -3.402823466e38f;
        #pragma unroll
        for (int nj = 0; nj < 4; nj++) {
            pm0 = fmaxf(pm0, fmaxf(sf[nj][0], sf[nj][1]));
            pm1 = fmaxf(pm1, fmaxf(sf[nj][2], sf[nj][3]));
        }
        pm0 = fmaxf(pm0, __shfl_xor_sync(0xffffffffu, pm0, 1));
        pm0 = fmaxf(pm0, __shfl_xor_sync(0xffffffffu, pm0, 2));
        pm1 = fmaxf(pm1, __shfl_xor_sync(0xffffffffu, pm1, 1));
        pm1 = fmaxf(pm1, __shfl_xor_sync(0xffffffffu, pm1, 2));
        if (t4 == 0) {
            SMAX[mr*2 + wx] = pm0;
            SMAX[(mr+8)*2 + wx] = pm1;
        }
        __syncthreads();
        float cmax0 = fmaxf(SMAX[mr*2], SMAX[mr*2+1]);
        float cmax1 = fmaxf(SMAX[(mr+8)*2], SMAX[(mr+8)*2+1]);

        float mn0 = fmaxf(m0r, cmax0);
        float mn1 = fmaxf(m1r, cmax1);
        float corr0 = __expf(m0r - mn0);
        float corr1 = __expf(m1r - mn1);
        m0r = mn0; m1r = mn1;

        // exp + partial sums + write P transposed [key][row] (single tf32)
        float ps0 = 0.f, ps1 = 0.f;
        #pragma unroll
        for (int nj = 0; nj < 4; nj++) {
            int j0 = wx*32 + nj*8 + 2*t4;
            float p00 = __expf(sf[nj][0] - mn0);
            float p01 = __expf(sf[nj][1] - mn0);
            float p10 = __expf(sf[nj][2] - mn1);
            float p11 = __expf(sf[nj][3] - mn1);
            ps0 += p00 + p01;
            ps1 += p10 + p11;
            PT[j0*FPAD + mr]       = f2tf32(p00);
            PT[(j0+1)*FPAD + mr]   = f2tf32(p01);
            PT[j0*FPAD + mr+8]     = f2tf32(p10);
            PT[(j0+1)*FPAD + mr+8] = f2tf32(p11);
        }
        ps0 += __shfl_xor_sync(0xffffffffu, ps0, 1);
        ps0 += __shfl_xor_sync(0xffffffffu, ps0, 2);
        ps1 += __shfl_xor_sync(0xffffffffu, ps1, 1);
        ps1 += __shfl_xor_sync(0xffffffffu, ps1, 2);
        if (t4 == 0) {
            SSUM[mr*2 + wx] = ps0;
            SSUM[(mr+8)*2 + wx] = ps1;
        }

        // rescale accumulators
        #pragma unroll
        for (int nj = 0; nj < 4; nj++) {
            acc[nj][0] *= corr0; acc[nj][1] *= corr0;
            acc[nj][2] *= corr1; acc[nj][3] *= corr1;
        }
        __syncthreads();

        l0 = l0*corr0 + SSUM[mr*2] + SSUM[mr*2+1];
        l1 = l1*corr1 + SSUM[(mr+8)*2] + SSUM[(mr+8)*2+1];

        // ---- acc += P @ V (single tf32) ----
        #pragma unroll
        for (int kk = 0; kk < 64; kk += 8) {
            unsigned ap[4];
            ap[0] = PT[(kk+t4)*FPAD + mr];
            ap[1] = PT[(kk+t4)*FPAD + mr + 8];
            ap[2] = PT[(kk+t4+4)*FPAD + mr];
            ap[3] = PT[(kk+t4+4)*FPAD + mr + 8];
            #pragma unroll
            for (int nj = 0; nj < 4; nj++) {
                int nc = wx*32 + nj*8 + g;
                unsigned bv[2] = { VS[(kk+t4)*FPAD + nc], VS[(kk+t4+4)*FPAD + nc] };
                mma_tf32(acc[nj], ap, bv);
            }
        }
        __syncthreads();
    }

    // epilogue
    float inv0 = 1.f / l0, inv1 = 1.f / l1;
    #pragma unroll
    for (int nj = 0; nj < 4; nj++) {
        int col = h*oColMul + oColAdd + wx*32 + nj*8 + 2*t4;
        long r0 = (long)(qrow0 + mr)*ostride + col;
        long r1 = (long)(qrow0 + mr + 8)*ostride + col;
        *(float2*)&Out[r0] = make_float2(acc[nj][0]*inv0, acc[nj][1]*inv0);
        *(float2*)&Out[r1] = make_float2(acc[nj][2]*inv1, acc[nj][3]*inv1);
    }
}

// ---------------- memories copy ----------------
__global__ void memories_kernel(const float* __restrict__ qkv, float* __restrict__ out)
{
    int idx = blockIdx.x*256 + threadIdx.x;
    if (idx >= 2*HEADS*WIDTH*HD) return;
    int d = idx & 63;
    int i = (idx >> 6) & 511;
    int h = (idx >> 15) & 15;
    int s = idx >> 19;
    out[idx] = qkv[(long)(3584+i)*3072 + (s ? 2048 : 1024) + h*HD + d];
}

// ---------------- new_states ----------------
__global__ void newstates_kernel(const float* __restrict__ gz, const float* __restrict__ bg,
        const float* __restrict__ beta, const float* __restrict__ init_state,
        float* __restrict__ out)
{
    int idx = blockIdx.x*256 + threadIdx.x;
    if (idx >= NST*DIMM) return;
    int c = idx & (DIMM-1);
    float sig = 1.f/(1.f+expf(-beta[c]));
    float z = gz[idx] + bg[c];
    out[idx] = sig*z + (1.f-sig)*init_state[idx];
}

// ---------------- host launch ----------------
static float* symaddr(const void* s)
{
    void* p = nullptr;
    cudaGetSymbolAddress(&p, s);
    return (float*)p;
}

extern "C" void kernel_launch(void* const* d_in, const int* in_sizes, int n_in,
                              void* d_out, int out_size)
{
    const float* x       = (const float*)d_in[0];
    const float* bias    = (const float*)d_in[1];
    const float* gamma   = (const float*)d_in[2];
    const float* w_qkv   = (const float*)d_in[3];
    const float* q_scale = (const float*)d_in[4];
    const float* k_scale = (const float*)d_in[5];
    const float* w_out   = (const float*)d_in[6];
    const float* s_gamma = (const float*)d_in[7];
    const float* w_q2s   = (const float*)d_in[8];
    const float* w_qfs   = (const float*)d_in[9];
    const float* w_sqkv  = (const float*)d_in[10];
    const float* init_st = (const float*)d_in[11];
    const float* pos_ids = (const float*)d_in[12];
    const float* w_sout  = (const float*)d_in[13];
    const float* ts_q    = (const float*)d_in[14];
    const float* ts_k    = (const float*)d_in[15];
    const float* ss_q    = (const float*)d_in[16];
    const float* ss_k    = (const float*)d_in[17];
    const float* fs_q    = (const float*)d_in[18];
    const float* fs_k    = (const float*)d_in[19];
    const float* w_gate  = (const float*)d_in[20];
    const float* b_gate  = (const float*)d_in[21];
    const float* beta    = (const float*)d_in[22];
    float* out = (float*)d_out;

    float* xn   = symaddr(g_xn);
    float* qkv  = symaddr(g_qkv);
    float* q2s  = symaddr(g_q2s);
    float* sqkv = symaddr(g_state_qkv);
    float* st   = symaddr(g_st);
    float* qfsr = symaddr(g_qfs_raw);
    float* qnm  = symaddr(g_qn_main);
    float* knm  = symaddr(g_kn_main);
    float* qnts = symaddr(g_qn_ts);
    float* knts = symaddr(g_kn_ts);
    float* qnss = symaddr(g_qn_ss);
    float* knss = symaddr(g_kn_ss);
    float* qnfs = symaddr(g_qn_fs);
    float* knfs = symaddr(g_kn_fs);
    float* aout = symaddr(g_attn_out);
    float* tout = symaddr(g_ts_out);
    float* scat = symaddr(g_state_cat);
    float* so   = symaddr(g_so);
    float* zb   = symaddr(g_z);

    cudaFuncSetAttribute(flashmma, cudaFuncAttributeMaxDynamicSharedMemorySize, FLASH_SMEM);

    // 1) layernorms
    ln_kernel<<<NSEQ, 256>>>(x, gamma, nullptr, xn);
    ln_kernel<<<NST, 256>>>(init_st, s_gamma, pos_ids, st);

    // 2) projections (TF32 tensor cores)
    tgemm<<<dim3(3072/128, NSEQ/128), 256>>>(xn, w_qkv, qkv, NSEQ, 3072, DIMM, 0);
    tgemm<<<dim3(DIMM/128, NSEQ/128), 256>>>(xn, w_q2s, q2s, NSEQ, DIMM, DIMM, 0);
    tgemm<<<dim3(3072/128, NST/128), 256>>>(init_st, w_sqkv, sqkv, NST, 3072, DIMM, 0);
    tgemm<<<dim3(DIMM/128, NST/128), 256>>>(st, w_qfs, qfsr, NST, DIMM, DIMM, 0);

    // 3) l2norm + scale, head-major
    norm_heads<<<dim3(NSEQ, HEADS), 64>>>(qkv, 3072, 0,    0,    q_scale, qnm,  NSEQ);
    norm_heads<<<dim3(NSEQ, HEADS), 64>>>(qkv, 3072, 1024, 0,    k_scale, knm,  NSEQ);
    norm_heads<<<dim3(NSEQ, HEADS), 64>>>(q2s, 1024, 0,    0,    ts_q,    qnts, NSEQ);
    norm_heads<<<dim3(NST,  HEADS), 64>>>(sqkv, 3072, 1024, 0,   ts_k,    knts, NST);
    norm_heads<<<dim3(NST,  HEADS), 64>>>(sqkv, 3072, 0,    0,   ss_q,    qnss, NST);
    norm_heads<<<dim3(NST,  HEADS), 64>>>(sqkv, 3072, 1024, 0,   ss_k,    knss, NST);
    norm_heads<<<dim3(NST,  HEADS), 64>>>(qfsr, 1024, 0,    0,   fs_q,    qnfs, NST);
    norm_heads<<<dim3(NST,  HEADS), 64>>>(qkv,  3072, 1024, 3584, fs_k,   knfs, NST);

    // 4) fused attentions
    flashmma<<<dim3(WIDTH/64, HEADS*NW), 256, FLASH_SMEM>>>(
        qnm, NSEQ, knm, NSEQ, qkv, 3072, HD, 2048, 0, bias,
        aout, DIMM, HD, 0, KEYW, NW);
    flashmma<<<dim3(NSEQ/64, HEADS), 256, FLASH_SMEM>>>(
        qnts, NSEQ, knts, NST, sqkv, 3072, HD, 2048, 0, nullptr,
        tout, DIMM, HD, 0, NST, 1);
    flashmma<<<dim3(NST/64, HEADS), 256, FLASH_SMEM>>>(
        qnss, NST, knss, NST, sqkv, 3072, HD, 2048, 0, nullptr,
        scat, 2*DIMM, 2*HD, 0, NST, 1);
    flashmma<<<dim3(NST/64, HEADS), 256, FLASH_SMEM>>>(
        qnfs, NST, knfs, NST, qkv, 3072, HD, 2048, 3584, nullptr,
        scat, 2*DIMM, 2*HD, HD, NST, 1);

    // 5) output projections
    tgemm<<<dim3(DIMM/128, NSEQ/128), 256>>>(aout, w_out, out, NSEQ, DIMM, DIMM, 0);
    tgemm<<<dim3(DIMM/128, NSEQ/128), 256>>>(tout, w_out + (long)DIMM*DIMM, out, NSEQ, DIMM, DIMM, 1);

    // 6) memories
    memories_kernel<<<(2*HEADS*WIDTH*HD)/256, 256>>>(qkv, out + (long)NSEQ*DIMM);

    // 7) state output path
    tgemm<<<dim3(DIMM/128, NST/128), 256>>>(scat, w_sout, so, NST, DIMM, 2*DIMM, 0);
    tgemm<<<dim3(DIMM/128, NST/128), 256>>>(so, w_gate, zb, NST, DIMM, DIMM, 0);
    newstates_kernel<<<(NST*DIMM)/256, 256>>>(zb, b_gate, beta, init_st,
            out + (long)NSEQ*DIMM + 2*HEADS*WIDTH*HD);
}

// round 10
// speedup vs baseline: 1.6333x; 1.0863x over previous
#include <cuda_runtime.h>
#include <math.h>

#define NSEQ  4096
#define DIMM  1024
#define HEADS 16
#define HD    64
#define WIDTH 512
#define NW    8
#define NST   512
#define KEYW  1024

// ---------------- scratch ----------------
__device__ float g_xn[NSEQ*DIMM];
__device__ float g_qkv[NSEQ*3*DIMM];
__device__ float g_q2s[NSEQ*DIMM];
__device__ float g_state_qkv[NST*3*DIMM];
__device__ float g_st[NST*DIMM];
__device__ float g_qfs_raw[NST*DIMM];

__device__ float g_qn_main[HEADS*NSEQ*HD];
__device__ float g_kn_main[HEADS*NSEQ*HD];
__device__ float g_qn_ts[HEADS*NSEQ*HD];
__device__ float g_kn_ts[HEADS*NST*HD];
__device__ float g_qn_ss[HEADS*NST*HD];
__device__ float g_kn_ss[HEADS*NST*HD];
__device__ float g_qn_fs[HEADS*NST*HD];
__device__ float g_kn_fs[HEADS*NST*HD];

__device__ float g_cat[NSEQ*2*DIMM];       // [attn_out | ts_out]
__device__ float g_state_cat[NST*2*DIMM];
__device__ float g_so[NST*DIMM];
__device__ float g_z[NST*DIMM];

// ---------------- layernorm ----------------
__global__ void __launch_bounds__(256) ln_kernel(const float* __restrict__ x,
        const float* __restrict__ gamma, const float* __restrict__ pos,
        float* __restrict__ out)
{
    int row = blockIdx.x;
    const float* xr = x + (long)row*DIMM;
    float* orow = out + (long)row*DIMM;
    __shared__ float red[256];
    float s = 0.f, s2 = 0.f;
    for (int i = threadIdx.x; i < DIMM; i += 256) { float v = xr[i]; s += v; s2 += v*v; }
    red[threadIdx.x] = s; __syncthreads();
    for (int o = 128; o; o >>= 1) { if (threadIdx.x < o) red[threadIdx.x] += red[threadIdx.x+o]; __syncthreads(); }
    float mu = red[0] * (1.f/DIMM);
    __syncthreads();
    red[threadIdx.x] = s2; __syncthreads();
    for (int o = 128; o; o >>= 1) { if (threadIdx.x < o) red[threadIdx.x] += red[threadIdx.x+o]; __syncthreads(); }
    float var = red[0] * (1.f/DIMM) - mu*mu;
    float inv = rsqrtf(var + 1e-5f);
    for (int i = threadIdx.x; i < DIMM; i += 256) {
        float v = (xr[i]-mu)*inv*gamma[i];
        if (pos) v += pos[(long)row*DIMM + i];
        orow[i] = v;
    }
}

// ---------------- TF32 helpers ----------------
__device__ __forceinline__ unsigned f2tf32(float f)
{
    unsigned r;
    asm("cvt.rna.tf32.f32 %0, %1;" : "=r"(r) : "f"(f));
    return r;
}

__device__ __forceinline__ void mma_tf32(float c[4], const unsigned a[4], const unsigned b[2])
{
    asm volatile(
        "mma.sync.aligned.m16n8k8.row.col.f32.tf32.tf32.f32 "
        "{%0,%1,%2,%3}, {%4,%5,%6,%7}, {%8,%9}, {%0,%1,%2,%3};"
        : "+f"(c[0]), "+f"(c[1]), "+f"(c[2]), "+f"(c[3])
        : "r"(a[0]), "r"(a[1]), "r"(a[2]), "r"(a[3]), "r"(b[0]), "r"(b[1]));
}

__device__ __forceinline__ void cp16(float* dst, const float* src)
{
    unsigned d = (unsigned)__cvta_generic_to_shared(dst);
    asm volatile("cp.async.cg.shared.global [%0], [%1], 16;" :: "r"(d), "l"(src));
}

// ---------------- TF32 GEMM: cp.async 4-stage pipeline ----------------
// A tiles stored raw-float [m][k] stride 20; B tiles [k][n] stride 132.
#define TG_STAGES 4
#define TG_ASTRIDE 20
#define TG_ATILE (128*TG_ASTRIDE)   // 2560 floats
#define TG_BTILE (16*132)           // 2112 floats
#define TGEMM_SMEM (TG_STAGES*(TG_ATILE + TG_BTILE)*4)

__global__ void __launch_bounds__(256) tgemm(const float* __restrict__ A,
        const float* __restrict__ B, float* __restrict__ C,
        int M, int N, int K, int accum)
{
    extern __shared__ float tsm[];
    float* Asm = tsm;                              // TG_STAGES * TG_ATILE
    float* Bsm = tsm + TG_STAGES*TG_ATILE;         // TG_STAGES * TG_BTILE

    int tid = threadIdx.x;
    int warp = tid >> 5, lane = tid & 31;
    int wy = warp >> 1, wx = warp & 1;
    int g = lane >> 2, t4 = lane & 3;
    int m0 = blockIdx.y*128, n0 = blockIdx.x*128;

    int nkt = K >> 4;

    auto issue = [&](int kt) {
        int buf = kt & (TG_STAGES-1);
        float* as = Asm + buf*TG_ATILE;
        float* bs = Bsm + buf*TG_BTILE;
        int row = tid >> 2, seg = (tid & 3)*4;
        const float* a0 = A + (long)(m0 + row)*K + kt*16 + seg;
        cp16(as + row*TG_ASTRIDE + seg, a0);
        cp16(as + (row+64)*TG_ASTRIDE + seg, a0 + (long)64*K);
        int krow = tid >> 5, col = (tid & 31)*4;
        const float* b0 = B + (long)(kt*16 + krow)*N + n0 + col;
        cp16(bs + krow*132 + col, b0);
        cp16(bs + (krow+8)*132 + col, b0 + (long)8*N);
        asm volatile("cp.async.commit_group;");
    };

    float acc[2][8][4];
    #pragma unroll
    for (int mi = 0; mi < 2; mi++)
        #pragma unroll
        for (int nj = 0; nj < 8; nj++)
            #pragma unroll
            for (int c = 0; c < 4; c++) acc[mi][nj][c] = 0.f;

    // prologue: fill pipeline
    #pragma unroll
    for (int s = 0; s < TG_STAGES-1; s++)
        if (s < nkt) issue(s);

    for (int kt = 0; kt < nkt; kt++) {
        asm volatile("cp.async.wait_group %0;" :: "n"(TG_STAGES-2));
        __syncthreads();

        if (kt + TG_STAGES-1 < nkt) issue(kt + TG_STAGES-1);

        int buf = kt & (TG_STAGES-1);
        const float* as = Asm + buf*TG_ATILE;
        const float* bs = Bsm + buf*TG_BTILE;

        #pragma unroll
        for (int ks = 0; ks < 2; ks++) {
            int kk = ks*8;
            unsigned af[2][4], bf[8][2];
            #pragma unroll
            for (int mi = 0; mi < 2; mi++) {
                int mr = wy*32 + mi*16 + g;
                af[mi][0] = f2tf32(as[mr*TG_ASTRIDE + kk + t4]);
                af[mi][1] = f2tf32(as[(mr+8)*TG_ASTRIDE + kk + t4]);
                af[mi][2] = f2tf32(as[mr*TG_ASTRIDE + kk + t4 + 4]);
                af[mi][3] = f2tf32(as[(mr+8)*TG_ASTRIDE + kk + t4 + 4]);
            }
            #pragma unroll
            for (int nj = 0; nj < 8; nj++) {
                int nc = wx*64 + nj*8 + g;
                bf[nj][0] = f2tf32(bs[(kk + t4)*132 + nc]);
                bf[nj][1] = f2tf32(bs[(kk + t4 + 4)*132 + nc]);
            }
            #pragma unroll
            for (int mi = 0; mi < 2; mi++)
                #pragma unroll
                for (int nj = 0; nj < 8; nj++)
                    mma_tf32(acc[mi][nj], af[mi], bf[nj]);
        }
    }

    #pragma unroll
    for (int mi = 0; mi < 2; mi++) {
        #pragma unroll
        for (int nj = 0; nj < 8; nj++) {
            int row = m0 + wy*32 + mi*16 + g;
            int col = n0 + wx*64 + nj*8 + t4*2;
            float* p0 = &C[(long)row*N + col];
            float* p1 = &C[(long)(row+8)*N + col];
            float2 v0 = make_float2(acc[mi][nj][0], acc[mi][nj][1]);
            float2 v1 = make_float2(acc[mi][nj][2], acc[mi][nj][3]);
            if (accum) {
                float2 o0 = *(float2*)p0, o1 = *(float2*)p1;
                v0.x += o0.x; v0.y += o0.y; v1.x += o1.x; v1.y += o1.y;
            }
            *(float2*)p0 = v0;
            *(float2*)p1 = v1;
        }
    }
}

// ---------------- l2norm + scale, head-major ----------------
__global__ void norm_heads(const float* __restrict__ src, int srcStride, int colOff,
        int rowOff, const float* __restrict__ scale, float* __restrict__ dst, int nrows)
{
    int row = blockIdx.x, h = blockIdx.y, d = threadIdx.x;
    float v = src[(long)(rowOff+row)*srcStride + colOff + h*HD + d];
    float s = v*v;
    #pragma unroll
    for (int o = 16; o; o >>= 1) s += __shfl_xor_sync(0xffffffffu, s, o);
    __shared__ float sh[2];
    if ((d & 31) == 0) sh[d>>5] = s;
    __syncthreads();
    float inv = 1.f / fmaxf(sqrtf(sh[0]+sh[1]), 1e-12f);
    dst[((long)h*nrows + row)*HD + d] = v*inv*scale[d];
}

// ---------------- flash attention: QK^T compensated tf32, PV single tf32 ----------------
#define FPAD 68
#define TILEU (64*FPAD)
#define FLASH_SMEM (6*TILEU*4 + 256*4)

__global__ void __launch_bounds__(256, 2) flashmma(
        const float* __restrict__ Q, int qHeadRows,
        const float* __restrict__ Kh, int kHeadRows,
        const float* __restrict__ Vall, long vstride, int vColHeadMul, int vColAdd,
        int vRowExtra,
        const float* __restrict__ bias,
        float* __restrict__ Out, long ostride, int oColMul, int oColAdd,
        int L, int nwin)
{
    extern __shared__ unsigned usm[];
    unsigned* QHI = usm;
    unsigned* QLO = usm + TILEU;
    unsigned* KHI = usm + 2*TILEU;
    unsigned* KLO = usm + 3*TILEU;
    unsigned* VS  = usm + 4*TILEU;
    unsigned* PT  = usm + 5*TILEU;
    float* SMAX = (float*)(usm + 6*TILEU);   // [64][2]
    float* SSUM = SMAX + 128;                // [64][2]

    int tid = threadIdx.x;
    int warp = tid >> 5, lane = tid & 31;
    int wy = warp >> 1, wx = warp & 1;
    int g = lane >> 2, t4 = lane & 3;

    int z = blockIdx.y;
    int h = z / nwin, w = z - h*nwin;
    int winw = qHeadRows / nwin;
    int i0 = blockIdx.x*64;
    int qrow0 = w*winw + i0;
    int kOff = (nwin > 1) ? (w-1)*winw : 0;

    const float* Qblk = Q + ((long)h*qHeadRows + qrow0)*64;
    const float* Kbase = Kh + (long)h*kHeadRows*64;
    const float* Vbase = Vall + vColHeadMul*h + vColAdd;
    const float* biasH = bias ? bias + (long)h*WIDTH*KEYW : nullptr;

    // load Q, split hi/lo, store [d][row]
    #pragma unroll
    for (int t = 0; t < 16; t++) {
        int e = tid + t*256;
        int r = e >> 6, c = e & 63;
        float v = Qblk[(long)r*64 + c];
        unsigned hi = f2tf32(v);
        QHI[c*FPAD + r] = hi;
        QLO[c*FPAD + r] = f2tf32(v - __uint_as_float(hi));
    }

    int mr = wy*16 + g;
    float m0r = -3.402823466e38f, m1r = -3.402823466e38f;
    float l0 = 0.f, l1 = 0.f;
    float acc[4][4];
    #pragma unroll
    for (int nj = 0; nj < 4; nj++)
        #pragma unroll
        for (int c = 0; c < 4; c++) acc[nj][c] = 0.f;

    int Lq = biasH ? (i0 + 576) : L;
    if (Lq > L) Lq = L;

    for (int c0 = 0; c0 < Lq; c0 += 64) {
        // load + split K [d][key]; V single [key][d]
        #pragma unroll
        for (int t = 0; t < 16; t++) {
            int e = tid + t*256;
            int r = e >> 6, cc = e & 63;
            int kr = kOff + c0 + r;
            float kv = (kr >= 0) ? Kbase[(long)kr*64 + cc] : 0.f;
            float vv = (kr >= 0) ? Vbase[(long)(kr + vRowExtra)*vstride + cc] : 0.f;
            unsigned khi = f2tf32(kv);
            KHI[cc*FPAD + r] = khi;
            KLO[cc*FPAD + r] = f2tf32(kv - __uint_as_float(khi));
            VS[r*FPAD + cc] = f2tf32(vv);
        }
        __syncthreads();

        // ---- S = Q @ K^T (compensated) ----
        float sf[4][4];
        #pragma unroll
        for (int nj = 0; nj < 4; nj++)
            #pragma unroll
            for (int c = 0; c < 4; c++) sf[nj][c] = 0.f;

        #pragma unroll
        for (int kk = 0; kk < 64; kk += 8) {
            unsigned ahi[4], alo[4];
            ahi[0] = QHI[(kk+t4)*FPAD + mr];
            ahi[1] = QHI[(kk+t4)*FPAD + mr + 8];
            ahi[2] = QHI[(kk+t4+4)*FPAD + mr];
            ahi[3] = QHI[(kk+t4+4)*FPAD + mr + 8];
            alo[0] = QLO[(kk+t4)*FPAD + mr];
            alo[1] = QLO[(kk+t4)*FPAD + mr + 8];
            alo[2] = QLO[(kk+t4+4)*FPAD + mr];
            alo[3] = QLO[(kk+t4+4)*FPAD + mr + 8];
            #pragma unroll
            for (int nj = 0; nj < 4; nj++) {
                int nc = wx*32 + nj*8 + g;
                unsigned bhi[2] = { KHI[(kk+t4)*FPAD + nc], KHI[(kk+t4+4)*FPAD + nc] };
                unsigned blo[2] = { KLO[(kk+t4)*FPAD + nc], KLO[(kk+t4+4)*FPAD + nc] };
                mma_tf32(sf[nj], ahi, bhi);
                mma_tf32(sf[nj], alo, bhi);
                mma_tf32(sf[nj], ahi, blo);
            }
        }

        // ---- scale + bias + mask ----
        int ir0 = i0 + mr, ir1 = ir0 + 8;
        #pragma unroll
        for (int nj = 0; nj < 4; nj++) {
            int j0 = c0 + wx*32 + nj*8 + 2*t4;
            #pragma unroll
            for (int c = 0; c < 4; c++) sf[nj][c] *= 8.f;
            if (biasH) {
                float2 b0 = *(const float2*)&biasH[(long)ir0*KEYW + j0];
                float2 b1 = *(const float2*)&biasH[(long)ir1*KEYW + j0];
                sf[nj][0] += b0.x; sf[nj][1] += b0.y;
                sf[nj][2] += b1.x; sf[nj][3] += b1.y;
                if (j0     > ir0 + 512) sf[nj][0] = -3.402823466e38f;
                if (j0 + 1 > ir0 + 512) sf[nj][1] = -3.402823466e38f;
                if (j0     > ir1 + 512) sf[nj][2] = -3.402823466e38f;
                if (j0 + 1 > ir1 + 512) sf[nj][3] = -3.402823466e38f;
            }
        }

        // ---- row max ----
        float pm0 = -3.402823466e38f, pm1 = -3.402823466e38f;
        #pragma unroll
        for (int nj = 0; nj < 4; nj++) {
            pm0 = fmaxf(pm0, fmaxf(sf[nj][0], sf[nj][1]));
            pm1 = fmaxf(pm1, fmaxf(sf[nj][2], sf[nj][3]));
        }
        pm0 = fmaxf(pm0, __shfl_xor_sync(0xffffffffu, pm0, 1));
        pm0 = fmaxf(pm0, __shfl_xor_sync(0xffffffffu, pm0, 2));
        pm1 = fmaxf(pm1, __shfl_xor_sync(0xffffffffu, pm1, 1));
        pm1 = fmaxf(pm1, __shfl_xor_sync(0xffffffffu, pm1, 2));
        if (t4 == 0) {
            SMAX[mr*2 + wx] = pm0;
            SMAX[(mr+8)*2 + wx] = pm1;
        }
        __syncthreads();
        float cmax0 = fmaxf(SMAX[mr*2], SMAX[mr*2+1]);
        float cmax1 = fmaxf(SMAX[(mr+8)*2], SMAX[(mr+8)*2+1]);

        float mn0 = fmaxf(m0r, cmax0);
        float mn1 = fmaxf(m1r, cmax1);
        float corr0 = __expf(m0r - mn0);
        float corr1 = __expf(m1r - mn1);
        m0r = mn0; m1r = mn1;

        // exp + partial sums + write P transposed [key][row] (single tf32)
        float ps0 = 0.f, ps1 = 0.f;
        #pragma unroll
        for (int nj = 0; nj < 4; nj++) {
            int j0 = wx*32 + nj*8 + 2*t4;
            float p00 = __expf(sf[nj][0] - mn0);
            float p01 = __expf(sf[nj][1] - mn0);
            float p10 = __expf(sf[nj][2] - mn1);
            float p11 = __expf(sf[nj][3] - mn1);
            ps0 += p00 + p01;
            ps1 += p10 + p11;
            PT[j0*FPAD + mr]       = f2tf32(p00);
            PT[(j0+1)*FPAD + mr]   = f2tf32(p01);
            PT[j0*FPAD + mr+8]     = f2tf32(p10);
            PT[(j0+1)*FPAD + mr+8] = f2tf32(p11);
        }
        ps0 += __shfl_xor_sync(0xffffffffu, ps0, 1);
        ps0 += __shfl_xor_sync(0xffffffffu, ps0, 2);
        ps1 += __shfl_xor_sync(0xffffffffu, ps1, 1);
        ps1 += __shfl_xor_sync(0xffffffffu, ps1, 2);
        if (t4 == 0) {
            SSUM[mr*2 + wx] = ps0;
            SSUM[(mr+8)*2 + wx] = ps1;
        }

        // rescale accumulators
        #pragma unroll
        for (int nj = 0; nj < 4; nj++) {
            acc[nj][0] *= corr0; acc[nj][1] *= corr0;
            acc[nj][2] *= corr1; acc[nj][3] *= corr1;
        }
        __syncthreads();

        l0 = l0*corr0 + SSUM[mr*2] + SSUM[mr*2+1];
        l1 = l1*corr1 + SSUM[(mr+8)*2] + SSUM[(mr+8)*2+1];

        // ---- acc += P @ V (single tf32) ----
        #pragma unroll
        for (int kk = 0; kk < 64; kk += 8) {
            unsigned ap[4];
            ap[0] = PT[(kk+t4)*FPAD + mr];
            ap[1] = PT[(kk+t4)*FPAD + mr + 8];
            ap[2] = PT[(kk+t4+4)*FPAD + mr];
            ap[3] = PT[(kk+t4+4)*FPAD + mr + 8];
            #pragma unroll
            for (int nj = 0; nj < 4; nj++) {
                int nc = wx*32 + nj*8 + g;
                unsigned bv[2] = { VS[(kk+t4)*FPAD + nc], VS[(kk+t4+4)*FPAD + nc] };
                mma_tf32(acc[nj], ap, bv);
            }
        }
        __syncthreads();
    }

    // epilogue
    float inv0 = 1.f / l0, inv1 = 1.f / l1;
    #pragma unroll
    for (int nj = 0; nj < 4; nj++) {
        int col = h*oColMul + oColAdd + wx*32 + nj*8 + 2*t4;
        long r0 = (long)(qrow0 + mr)*ostride + col;
        long r1 = (long)(qrow0 + mr + 8)*ostride + col;
        *(float2*)&Out[r0] = make_float2(acc[nj][0]*inv0, acc[nj][1]*inv0);
        *(float2*)&Out[r1] = make_float2(acc[nj][2]*inv1, acc[nj][3]*inv1);
    }
}

// ---------------- memories copy ----------------
__global__ void memories_kernel(const float* __restrict__ qkv, float* __restrict__ out)
{
    int idx = blockIdx.x*256 + threadIdx.x;
    if (idx >= 2*HEADS*WIDTH*HD) return;
    int d = idx & 63;
    int i = (idx >> 6) & 511;
    int h = (idx >> 15) & 15;
    int s = idx >> 19;
    out[idx] = qkv[(long)(3584+i)*3072 + (s ? 2048 : 1024) + h*HD + d];
}

// ---------------- new_states ----------------
__global__ void newstates_kernel(const float* __restrict__ gz, const float* __restrict__ bg,
        const float* __restrict__ beta, const float* __restrict__ init_state,
        float* __restrict__ out)
{
    int idx = blockIdx.x*256 + threadIdx.x;
    if (idx >= NST*DIMM) return;
    int c = idx & (DIMM-1);
    float sig = 1.f/(1.f+expf(-beta[c]));
    float z = gz[idx] + bg[c];
    out[idx] = sig*z + (1.f-sig)*init_state[idx];
}

// ---------------- host launch ----------------
static float* symaddr(const void* s)
{
    void* p = nullptr;
    cudaGetSymbolAddress(&p, s);
    return (float*)p;
}

extern "C" void kernel_launch(void* const* d_in, const int* in_sizes, int n_in,
                              void* d_out, int out_size)
{
    const float* x       = (const float*)d_in[0];
    const float* bias    = (const float*)d_in[1];
    const float* gamma   = (const float*)d_in[2];
    const float* w_qkv   = (const float*)d_in[3];
    const float* q_scale = (const float*)d_in[4];
    const float* k_scale = (const float*)d_in[5];
    const float* w_out   = (const float*)d_in[6];
    const float* s_gamma = (const float*)d_in[7];
    const float* w_q2s   = (const float*)d_in[8];
    const float* w_qfs   = (const float*)d_in[9];
    const float* w_sqkv  = (const float*)d_in[10];
    const float* init_st = (const float*)d_in[11];
    const float* pos_ids = (const float*)d_in[12];
    const float* w_sout  = (const float*)d_in[13];
    const float* ts_q    = (const float*)d_in[14];
    const float* ts_k    = (const float*)d_in[15];
    const float* ss_q    = (const float*)d_in[16];
    const float* ss_k    = (const float*)d_in[17];
    const float* fs_q    = (const float*)d_in[18];
    const float* fs_k    = (const float*)d_in[19];
    const float* w_gate  = (const float*)d_in[20];
    const float* b_gate  = (const float*)d_in[21];
    const float* beta    = (const float*)d_in[22];
    float* out = (float*)d_out;

    float* xn   = symaddr(g_xn);
    float* qkv  = symaddr(g_qkv);
    float* q2s  = symaddr(g_q2s);
    float* sqkv = symaddr(g_state_qkv);
    float* st   = symaddr(g_st);
    float* qfsr = symaddr(g_qfs_raw);
    float* qnm  = symaddr(g_qn_main);
    float* knm  = symaddr(g_kn_main);
    float* qnts = symaddr(g_qn_ts);
    float* knts = symaddr(g_kn_ts);
    float* qnss = symaddr(g_qn_ss);
    float* knss = symaddr(g_kn_ss);
    float* qnfs = symaddr(g_qn_fs);
    float* knfs = symaddr(g_kn_fs);
    float* cat  = symaddr(g_cat);
    float* scat = symaddr(g_state_cat);
    float* so   = symaddr(g_so);
    float* zb   = symaddr(g_z);

    cudaFuncSetAttribute(flashmma, cudaFuncAttributeMaxDynamicSharedMemorySize, FLASH_SMEM);
    cudaFuncSetAttribute(tgemm, cudaFuncAttributeMaxDynamicSharedMemorySize, TGEMM_SMEM);

    // 1) layernorms
    ln_kernel<<<NSEQ, 256>>>(x, gamma, nullptr, xn);
    ln_kernel<<<NST, 256>>>(init_st, s_gamma, pos_ids, st);

    // 2) projections (TF32 tensor cores, cp.async pipelined)
    tgemm<<<dim3(3072/128, NSEQ/128), 256, TGEMM_SMEM>>>(xn, w_qkv, qkv, NSEQ, 3072, DIMM, 0);
    tgemm<<<dim3(DIMM/128, NSEQ/128), 256, TGEMM_SMEM>>>(xn, w_q2s, q2s, NSEQ, DIMM, DIMM, 0);
    tgemm<<<dim3(3072/128, NST/128), 256, TGEMM_SMEM>>>(init_st, w_sqkv, sqkv, NST, 3072, DIMM, 0);
    tgemm<<<dim3(DIMM/128, NST/128), 256, TGEMM_SMEM>>>(st, w_qfs, qfsr, NST, DIMM, DIMM, 0);

    // 3) l2norm + scale, head-major
    norm_heads<<<dim3(NSEQ, HEADS), 64>>>(qkv, 3072, 0,    0,    q_scale, qnm,  NSEQ);
    norm_heads<<<dim3(NSEQ, HEADS), 64>>>(qkv, 3072, 1024, 0,    k_scale, knm,  NSEQ);
    norm_heads<<<dim3(NSEQ, HEADS), 64>>>(q2s, 1024, 0,    0,    ts_q,    qnts, NSEQ);
    norm_heads<<<dim3(NST,  HEADS), 64>>>(sqkv, 3072, 1024, 0,   ts_k,    knts, NST);
    norm_heads<<<dim3(NST,  HEADS), 64>>>(sqkv, 3072, 0,    0,   ss_q,    qnss, NST);
    norm_heads<<<dim3(NST,  HEADS), 64>>>(sqkv, 3072, 1024, 0,   ss_k,    knss, NST);
    norm_heads<<<dim3(NST,  HEADS), 64>>>(qfsr, 1024, 0,    0,   fs_q,    qnfs, NST);
    norm_heads<<<dim3(NST,  HEADS), 64>>>(qkv,  3072, 1024, 3584, fs_k,   knfs, NST);

    // 4) fused attentions — main + to_state write into the wide cat buffer
    flashmma<<<dim3(WIDTH/64, HEADS*NW), 256, FLASH_SMEM>>>(
        qnm, NSEQ, knm, NSEQ, qkv, 3072, HD, 2048, 0, bias,
        cat, 2*DIMM, HD, 0, KEYW, NW);
    flashmma<<<dim3(NSEQ/64, HEADS), 256, FLASH_SMEM>>>(
        qnts, NSEQ, knts, NST, sqkv, 3072, HD, 2048, 0, nullptr,
        cat, 2*DIMM, HD, DIMM, NST, 1);
    flashmma<<<dim3(NST/64, HEADS), 256, FLASH_SMEM>>>(
        qnss, NST, knss, NST, sqkv, 3072, HD, 2048, 0, nullptr,
        scat, 2*DIMM, 2*HD, 0, NST, 1);
    flashmma<<<dim3(NST/64, HEADS), 256, FLASH_SMEM>>>(
        qnfs, NST, knfs, NST, qkv, 3072, HD, 2048, 3584, nullptr,
        scat, 2*DIMM, 2*HD, HD, NST, 1);

    // 5) output projection: out = cat @ w_out (single K=2048 GEMM)
    tgemm<<<dim3(DIMM/128, NSEQ/128), 256, TGEMM_SMEM>>>(cat, w_out, out, NSEQ, DIMM, 2*DIMM, 0);

    // 6) memories
    memories_kernel<<<(2*HEADS*WIDTH*HD)/256, 256>>>(qkv, out + (long)NSEQ*DIMM);

    // 7) state output path
    tgemm<<<dim3(DIMM/128, NST/128), 256, TGEMM_SMEM>>>(scat, w_sout, so, NST, DIMM, 2*DIMM, 0);
    tgemm<<<dim3(DIMM/128, NST/128), 256, TGEMM_SMEM>>>(so, w_gate, zb, NST, DIMM, DIMM, 0);
    newstates_kernel<<<(NST*DIMM)/256, 256>>>(zb, b_gate, beta, init_st,
            out + (long)NSEQ*DIMM + 2*HEADS*WIDTH*HD);
}

// round 11
// speedup vs baseline: 1.9006x; 1.1637x over previous
#include <cuda_runtime.h>
#include <math.h>

#define NSEQ  4096
#define DIMM  1024
#define HEADS 16
#define HD    64
#define WIDTH 512
#define NW    8
#define NST   512
#define KEYW  1024

// ---------------- scratch ----------------
__device__ float g_xn[NSEQ*DIMM];
__device__ float g_qkv[NSEQ*3*DIMM];
__device__ float g_q2s[NSEQ*DIMM];
__device__ float g_state_qkv[NST*3*DIMM];
__device__ float g_st[NST*DIMM];
__device__ float g_qfs_raw[NST*DIMM];

__device__ float g_qn_main[HEADS*NSEQ*HD];
__device__ float g_kn_main[HEADS*NSEQ*HD];
__device__ float g_qn_ts[HEADS*NSEQ*HD];
__device__ float g_kn_ts[HEADS*NST*HD];
__device__ float g_qn_ss[HEADS*NST*HD];
__device__ float g_kn_ss[HEADS*NST*HD];
__device__ float g_qn_fs[HEADS*NST*HD];
__device__ float g_kn_fs[HEADS*NST*HD];

__device__ float g_cat[NSEQ*2*DIMM];       // [attn_out | ts_out]
__device__ float g_state_cat[NST*2*DIMM];
__device__ float g_so[NST*DIMM];
__device__ float g_z[NST*DIMM];

// ---------------- layernorm ----------------
__global__ void __launch_bounds__(256) ln_kernel(const float* __restrict__ x,
        const float* __restrict__ gamma, const float* __restrict__ pos,
        float* __restrict__ out)
{
    int row = blockIdx.x;
    const float* xr = x + (long)row*DIMM;
    float* orow = out + (long)row*DIMM;
    __shared__ float red[256];
    float s = 0.f, s2 = 0.f;
    for (int i = threadIdx.x; i < DIMM; i += 256) { float v = xr[i]; s += v; s2 += v*v; }
    red[threadIdx.x] = s; __syncthreads();
    for (int o = 128; o; o >>= 1) { if (threadIdx.x < o) red[threadIdx.x] += red[threadIdx.x+o]; __syncthreads(); }
    float mu = red[0] * (1.f/DIMM);
    __syncthreads();
    red[threadIdx.x] = s2; __syncthreads();
    for (int o = 128; o; o >>= 1) { if (threadIdx.x < o) red[threadIdx.x] += red[threadIdx.x+o]; __syncthreads(); }
    float var = red[0] * (1.f/DIMM) - mu*mu;
    float inv = rsqrtf(var + 1e-5f);
    for (int i = threadIdx.x; i < DIMM; i += 256) {
        float v = (xr[i]-mu)*inv*gamma[i];
        if (pos) v += pos[(long)row*DIMM + i];
        orow[i] = v;
    }
}

// ---------------- TF32 helpers ----------------
__device__ __forceinline__ unsigned f2tf32(float f)
{
    unsigned r;
    asm("cvt.rna.tf32.f32 %0, %1;" : "=r"(r) : "f"(f));
    return r;
}

__device__ __forceinline__ void mma_tf32(float c[4], const unsigned a[4], const unsigned b[2])
{
    asm volatile(
        "mma.sync.aligned.m16n8k8.row.col.f32.tf32.tf32.f32 "
        "{%0,%1,%2,%3}, {%4,%5,%6,%7}, {%8,%9}, {%0,%1,%2,%3};"
        : "+f"(c[0]), "+f"(c[1]), "+f"(c[2]), "+f"(c[3])
        : "r"(a[0]), "r"(a[1]), "r"(a[2]), "r"(a[3]), "r"(b[0]), "r"(b[1]));
}

__device__ __forceinline__ void cp16(float* dst, const float* src)
{
    unsigned d = (unsigned)__cvta_generic_to_shared(dst);
    asm volatile("cp.async.cg.shared.global [%0], [%1], 16;" :: "r"(d), "l"(src));
}

__device__ __forceinline__ void cp16p(float* dst, const float* src, int sz)
{
    unsigned d = (unsigned)__cvta_generic_to_shared(dst);
    asm volatile("cp.async.cg.shared.global [%0], [%1], 16, %2;" :: "r"(d), "l"(src), "r"(sz));
}

// ---------------- TF32 GEMM: cp.async 4-stage pipeline ----------------
#define TG_STAGES 4
#define TG_ASTRIDE 20
#define TG_ATILE (128*TG_ASTRIDE)
#define TG_BTILE (16*132)
#define TGEMM_SMEM (TG_STAGES*(TG_ATILE + TG_BTILE)*4)

__global__ void __launch_bounds__(256) tgemm(const float* __restrict__ A,
        const float* __restrict__ B, float* __restrict__ C,
        int M, int N, int K, int accum)
{
    extern __shared__ float tsm[];
    float* Asm = tsm;
    float* Bsm = tsm + TG_STAGES*TG_ATILE;

    int tid = threadIdx.x;
    int warp = tid >> 5, lane = tid & 31;
    int wy = warp >> 1, wx = warp & 1;
    int g = lane >> 2, t4 = lane & 3;
    int m0 = blockIdx.y*128, n0 = blockIdx.x*128;

    int nkt = K >> 4;

    auto issue = [&](int kt) {
        int buf = kt & (TG_STAGES-1);
        float* as = Asm + buf*TG_ATILE;
        float* bs = Bsm + buf*TG_BTILE;
        int row = tid >> 2, seg = (tid & 3)*4;
        const float* a0 = A + (long)(m0 + row)*K + kt*16 + seg;
        cp16(as + row*TG_ASTRIDE + seg, a0);
        cp16(as + (row+64)*TG_ASTRIDE + seg, a0 + (long)64*K);
        int krow = tid >> 5, col = (tid & 31)*4;
        const float* b0 = B + (long)(kt*16 + krow)*N + n0 + col;
        cp16(bs + krow*132 + col, b0);
        cp16(bs + (krow+8)*132 + col, b0 + (long)8*N);
        asm volatile("cp.async.commit_group;");
    };

    float acc[2][8][4];
    #pragma unroll
    for (int mi = 0; mi < 2; mi++)
        #pragma unroll
        for (int nj = 0; nj < 8; nj++)
            #pragma unroll
            for (int c = 0; c < 4; c++) acc[mi][nj][c] = 0.f;

    #pragma unroll
    for (int s = 0; s < TG_STAGES-1; s++)
        if (s < nkt) issue(s);

    for (int kt = 0; kt < nkt; kt++) {
        asm volatile("cp.async.wait_group %0;" :: "n"(TG_STAGES-2));
        __syncthreads();

        if (kt + TG_STAGES-1 < nkt) issue(kt + TG_STAGES-1);

        int buf = kt & (TG_STAGES-1);
        const float* as = Asm + buf*TG_ATILE;
        const float* bs = Bsm + buf*TG_BTILE;

        #pragma unroll
        for (int ks = 0; ks < 2; ks++) {
            int kk = ks*8;
            unsigned af[2][4], bf[8][2];
            #pragma unroll
            for (int mi = 0; mi < 2; mi++) {
                int mr = wy*32 + mi*16 + g;
                af[mi][0] = f2tf32(as[mr*TG_ASTRIDE + kk + t4]);
                af[mi][1] = f2tf32(as[(mr+8)*TG_ASTRIDE + kk + t4]);
                af[mi][2] = f2tf32(as[mr*TG_ASTRIDE + kk + t4 + 4]);
                af[mi][3] = f2tf32(as[(mr+8)*TG_ASTRIDE + kk + t4 + 4]);
            }
            #pragma unroll
            for (int nj = 0; nj < 8; nj++) {
                int nc = wx*64 + nj*8 + g;
                bf[nj][0] = f2tf32(bs[(kk + t4)*132 + nc]);
                bf[nj][1] = f2tf32(bs[(kk + t4 + 4)*132 + nc]);
            }
            #pragma unroll
            for (int mi = 0; mi < 2; mi++)
                #pragma unroll
                for (int nj = 0; nj < 8; nj++)
                    mma_tf32(acc[mi][nj], af[mi], bf[nj]);
        }
    }

    #pragma unroll
    for (int mi = 0; mi < 2; mi++) {
        #pragma unroll
        for (int nj = 0; nj < 8; nj++) {
            int row = m0 + wy*32 + mi*16 + g;
            int col = n0 + wx*64 + nj*8 + t4*2;
            float* p0 = &C[(long)row*N + col];
            float* p1 = &C[(long)(row+8)*N + col];
            float2 v0 = make_float2(acc[mi][nj][0], acc[mi][nj][1]);
            float2 v1 = make_float2(acc[mi][nj][2], acc[mi][nj][3]);
            if (accum) {
                float2 o0 = *(float2*)p0, o1 = *(float2*)p1;
                v0.x += o0.x; v0.y += o0.y; v1.x += o1.x; v1.y += o1.y;
            }
            *(float2*)p0 = v0;
            *(float2*)p1 = v1;
        }
    }
}

// ---------------- l2norm + scale, head-major ----------------
__global__ void norm_heads(const float* __restrict__ src, int srcStride, int colOff,
        int rowOff, const float* __restrict__ scale, float* __restrict__ dst, int nrows)
{
    int row = blockIdx.x, h = blockIdx.y, d = threadIdx.x;
    float v = src[(long)(rowOff+row)*srcStride + colOff + h*HD + d];
    float s = v*v;
    #pragma unroll
    for (int o = 16; o; o >>= 1) s += __shfl_xor_sync(0xffffffffu, s, o);
    __shared__ float sh[2];
    if ((d & 31) == 0) sh[d>>5] = s;
    __syncthreads();
    float inv = 1.f / fmaxf(sqrtf(sh[0]+sh[1]), 1e-12f);
    dst[((long)h*nrows + row)*HD + d] = v*inv*scale[d];
}

// ---------------- flash attention: cp.async K/V raw, split at fragment load ----------------
// Tiles: QHI, QLO (tf32 split, [d][row]); KRAW [key][d] raw float; VRAW x2 [key][d]; PT [key][row]
#define FPAD 68
#define TILEU (64*FPAD)
#define FLASH_SMEM (6*TILEU*4 + 256*4)

__global__ void __launch_bounds__(256, 2) flashmma(
        const float* __restrict__ Q, int qHeadRows,
        const float* __restrict__ Kh, int kHeadRows,
        const float* __restrict__ Vall, long vstride, int vColHeadMul, int vColAdd,
        int vRowExtra,
        const float* __restrict__ bias,
        float* __restrict__ Out, long ostride, int oColMul, int oColAdd,
        int L, int nwin)
{
    extern __shared__ unsigned usm[];
    unsigned* QHI = usm;
    unsigned* QLO = usm + TILEU;
    float* KR  = (float*)(usm + 2*TILEU);
    float* VR0 = (float*)(usm + 3*TILEU);
    float* VR1 = (float*)(usm + 4*TILEU);
    unsigned* PT = usm + 5*TILEU;
    float* SMAX = (float*)(usm + 6*TILEU);   // [64][2]
    float* SSUM = SMAX + 128;                // [64][2]

    int tid = threadIdx.x;
    int warp = tid >> 5, lane = tid & 31;
    int wy = warp >> 1, wx = warp & 1;
    int g = lane >> 2, t4 = lane & 3;

    int z = blockIdx.y;
    int h = z / nwin, w = z - h*nwin;
    int winw = qHeadRows / nwin;
    int i0 = blockIdx.x*64;
    int qrow0 = w*winw + i0;
    int kOff = (nwin > 1) ? (w-1)*winw : 0;

    const float* Qblk = Q + ((long)h*qHeadRows + qrow0)*64;
    const float* Kbase = Kh + (long)h*kHeadRows*64;
    const float* Vbase = Vall + vColHeadMul*h + vColAdd;
    const float* biasH = bias ? bias + (long)h*WIDTH*KEYW : nullptr;

    // async issue helpers: 64 keys x 64 floats, row stride FPAD, zfill for kr<0
    auto issueK = [&](int c0) {
        #pragma unroll
        for (int t = 0; t < 4; t++) {
            int c4 = tid + t*256;
            int key = c4 >> 4, seg = (c4 & 15)*4;
            int kr = kOff + c0 + key;
            cp16p(KR + key*FPAD + seg, Kbase + (long)kr*64 + seg, (kr >= 0) ? 16 : 0);
        }
        asm volatile("cp.async.commit_group;");
    };
    auto issueV = [&](int c0, float* VB) {
        #pragma unroll
        for (int t = 0; t < 4; t++) {
            int c4 = tid + t*256;
            int key = c4 >> 4, seg = (c4 & 15)*4;
            int kr = kOff + c0 + key;
            cp16p(VB + key*FPAD + seg, Vbase + (long)(kr + vRowExtra)*vstride + seg,
                  (kr >= 0) ? 16 : 0);
        }
        asm volatile("cp.async.commit_group;");
    };

    // load Q, split hi/lo, store [d][row]
    #pragma unroll
    for (int t = 0; t < 16; t++) {
        int e = tid + t*256;
        int r = e >> 6, c = e & 63;
        float v = Qblk[(long)r*64 + c];
        unsigned hi = f2tf32(v);
        QHI[c*FPAD + r] = hi;
        QLO[c*FPAD + r] = f2tf32(v - __uint_as_float(hi));
    }

    int mr = wy*16 + g;
    float m0r = -3.402823466e38f, m1r = -3.402823466e38f;
    float l0 = 0.f, l1 = 0.f;
    float acc[4][4];
    #pragma unroll
    for (int nj = 0; nj < 4; nj++)
        #pragma unroll
        for (int c = 0; c < 4; c++) acc[nj][c] = 0.f;

    int Lq = biasH ? (i0 + 576) : L;
    if (Lq > L) Lq = L;
    int nch = (Lq + 63) >> 6;

    // prologue: V(0) then K(0)
    issueV(0, VR0);
    issueK(0);

    for (int ci = 0; ci < nch; ci++) {
        int c0 = ci << 6;
        float* VB = (ci & 1) ? VR1 : VR0;
        bool more = (ci + 1 < nch);

        if (more) {
            issueV(c0 + 64, (ci & 1) ? VR0 : VR1);
            asm volatile("cp.async.wait_group 1;");
        } else {
            asm volatile("cp.async.wait_group 0;");
        }
        __syncthreads();

        // ---- S = Q @ K^T (compensated; K split at fragment load) ----
        float sf[4][4];
        #pragma unroll
        for (int nj = 0; nj < 4; nj++)
            #pragma unroll
            for (int c = 0; c < 4; c++) sf[nj][c] = 0.f;

        #pragma unroll
        for (int kk = 0; kk < 64; kk += 8) {
            unsigned ahi[4], alo[4];
            ahi[0] = QHI[(kk+t4)*FPAD + mr];
            ahi[1] = QHI[(kk+t4)*FPAD + mr + 8];
            ahi[2] = QHI[(kk+t4+4)*FPAD + mr];
            ahi[3] = QHI[(kk+t4+4)*FPAD + mr + 8];
            alo[0] = QLO[(kk+t4)*FPAD + mr];
            alo[1] = QLO[(kk+t4)*FPAD + mr + 8];
            alo[2] = QLO[(kk+t4+4)*FPAD + mr];
            alo[3] = QLO[(kk+t4+4)*FPAD + mr + 8];
            #pragma unroll
            for (int nj = 0; nj < 4; nj++) {
                int nc = wx*32 + nj*8 + g;
                float k0 = KR[nc*FPAD + kk + t4];
                float k1 = KR[nc*FPAD + kk + t4 + 4];
                unsigned bhi[2] = { f2tf32(k0), f2tf32(k1) };
                unsigned blo[2] = { f2tf32(k0 - __uint_as_float(bhi[0])),
                                    f2tf32(k1 - __uint_as_float(bhi[1])) };
                mma_tf32(sf[nj], ahi, bhi);
                mma_tf32(sf[nj], alo, bhi);
                mma_tf32(sf[nj], ahi, blo);
            }
        }

        // ---- scale + bias + mask ----
        int ir0 = i0 + mr, ir1 = ir0 + 8;
        #pragma unroll
        for (int nj = 0; nj < 4; nj++) {
            int j0 = c0 + wx*32 + nj*8 + 2*t4;
            #pragma unroll
            for (int c = 0; c < 4; c++) sf[nj][c] *= 8.f;
            if (biasH) {
                float2 b0 = *(const float2*)&biasH[(long)ir0*KEYW + j0];
                float2 b1 = *(const float2*)&biasH[(long)ir1*KEYW + j0];
                sf[nj][0] += b0.x; sf[nj][1] += b0.y;
                sf[nj][2] += b1.x; sf[nj][3] += b1.y;
                if (j0     > ir0 + 512) sf[nj][0] = -3.402823466e38f;
                if (j0 + 1 > ir0 + 512) sf[nj][1] = -3.402823466e38f;
                if (j0     > ir1 + 512) sf[nj][2] = -3.402823466e38f;
                if (j0 + 1 > ir1 + 512) sf[nj][3] = -3.402823466e38f;
            }
        }

        // ---- row max ----
        float pm0 = -3.402823466e38f, pm1 = -3.402823466e38f;
        #pragma unroll
        for (int nj = 0; nj < 4; nj++) {
            pm0 = fmaxf(pm0, fmaxf(sf[nj][0], sf[nj][1]));
            pm1 = fmaxf(pm1, fmaxf(sf[nj][2], sf[nj][3]));
        }
        pm0 = fmaxf(pm0, __shfl_xor_sync(0xffffffffu, pm0, 1));
        pm0 = fmaxf(pm0, __shfl_xor_sync(0xffffffffu, pm0, 2));
        pm1 = fmaxf(pm1, __shfl_xor_sync(0xffffffffu, pm1, 1));
        pm1 = fmaxf(pm1, __shfl_xor_sync(0xffffffffu, pm1, 2));
        if (t4 == 0) {
            SMAX[mr*2 + wx] = pm0;
            SMAX[(mr+8)*2 + wx] = pm1;
        }
        __syncthreads();

        // K buffer free now (all warps past QK) — prefetch next K
        if (more) issueK(c0 + 64);

        float cmax0 = fmaxf(SMAX[mr*2], SMAX[mr*2+1]);
        float cmax1 = fmaxf(SMAX[(mr+8)*2], SMAX[(mr+8)*2+1]);

        float mn0 = fmaxf(m0r, cmax0);
        float mn1 = fmaxf(m1r, cmax1);
        float corr0 = __expf(m0r - mn0);
        float corr1 = __expf(m1r - mn1);
        m0r = mn0; m1r = mn1;

        // exp + partial sums + write P transposed [key][row] (single tf32)
        float ps0 = 0.f, ps1 = 0.f;
        #pragma unroll
        for (int nj = 0; nj < 4; nj++) {
            int j0 = wx*32 + nj*8 + 2*t4;
            float p00 = __expf(sf[nj][0] - mn0);
            float p01 = __expf(sf[nj][1] - mn0);
            float p10 = __expf(sf[nj][2] - mn1);
            float p11 = __expf(sf[nj][3] - mn1);
            ps0 += p00 + p01;
            ps1 += p10 + p11;
            PT[j0*FPAD + mr]       = f2tf32(p00);
            PT[(j0+1)*FPAD + mr]   = f2tf32(p01);
            PT[j0*FPAD + mr+8]     = f2tf32(p10);
            PT[(j0+1)*FPAD + mr+8] = f2tf32(p11);
        }
        ps0 += __shfl_xor_sync(0xffffffffu, ps0, 1);
        ps0 += __shfl_xor_sync(0xffffffffu, ps0, 2);
        ps1 += __shfl_xor_sync(0xffffffffu, ps1, 1);
        ps1 += __shfl_xor_sync(0xffffffffu, ps1, 2);
        if (t4 == 0) {
            SSUM[mr*2 + wx] = ps0;
            SSUM[(mr+8)*2 + wx] = ps1;
        }

        // rescale accumulators
        #pragma unroll
        for (int nj = 0; nj < 4; nj++) {
            acc[nj][0] *= corr0; acc[nj][1] *= corr0;
            acc[nj][2] *= corr1; acc[nj][3] *= corr1;
        }
        __syncthreads();

        l0 = l0*corr0 + SSUM[mr*2] + SSUM[mr*2+1];
        l1 = l1*corr1 + SSUM[(mr+8)*2] + SSUM[(mr+8)*2+1];

        // ---- acc += P @ V (single tf32; V converted at fragment load) ----
        #pragma unroll
        for (int kk = 0; kk < 64; kk += 8) {
            unsigned ap[4];
            ap[0] = PT[(kk+t4)*FPAD + mr];
            ap[1] = PT[(kk+t4)*FPAD + mr + 8];
            ap[2] = PT[(kk+t4+4)*FPAD + mr];
            ap[3] = PT[(kk+t4+4)*FPAD + mr + 8];
            #pragma unroll
            for (int nj = 0; nj < 4; nj++) {
                int nc = wx*32 + nj*8 + g;
                unsigned bv[2] = { f2tf32(VB[(kk+t4)*FPAD + nc]),
                                   f2tf32(VB[(kk+t4+4)*FPAD + nc]) };
                mma_tf32(acc[nj], ap, bv);
            }
        }
        __syncthreads();
    }

    // epilogue
    float inv0 = 1.f / l0, inv1 = 1.f / l1;
    #pragma unroll
    for (int nj = 0; nj < 4; nj++) {
        int col = h*oColMul + oColAdd + wx*32 + nj*8 + 2*t4;
        long r0 = (long)(qrow0 + mr)*ostride + col;
        long r1 = (long)(qrow0 + mr + 8)*ostride + col;
        *(float2*)&Out[r0] = make_float2(acc[nj][0]*inv0, acc[nj][1]*inv0);
        *(float2*)&Out[r1] = make_float2(acc[nj][2]*inv1, acc[nj][3]*inv1);
    }
}

// ---------------- memories copy ----------------
__global__ void memories_kernel(const float* __restrict__ qkv, float* __restrict__ out)
{
    int idx = blockIdx.x*256 + threadIdx.x;
    if (idx >= 2*HEADS*WIDTH*HD) return;
    int d = idx & 63;
    int i = (idx >> 6) & 511;
    int h = (idx >> 15) & 15;
    int s = idx >> 19;
    out[idx] = qkv[(long)(3584+i)*3072 + (s ? 2048 : 1024) + h*HD + d];
}

// ---------------- new_states ----------------
__global__ void newstates_kernel(const float* __restrict__ gz, const float* __restrict__ bg,
        const float* __restrict__ beta, const float* __restrict__ init_state,
        float* __restrict__ out)
{
    int idx = blockIdx.x*256 + threadIdx.x;
    if (idx >= NST*DIMM) return;
    int c = idx & (DIMM-1);
    float sig = 1.f/(1.f+expf(-beta[c]));
    float z = gz[idx] + bg[c];
    out[idx] = sig*z + (1.f-sig)*init_state[idx];
}

// ---------------- host launch ----------------
static float* symaddr(const void* s)
{
    void* p = nullptr;
    cudaGetSymbolAddress(&p, s);
    return (float*)p;
}

extern "C" void kernel_launch(void* const* d_in, const int* in_sizes, int n_in,
                              void* d_out, int out_size)
{
    const float* x       = (const float*)d_in[0];
    const float* bias    = (const float*)d_in[1];
    const float* gamma   = (const float*)d_in[2];
    const float* w_qkv   = (const float*)d_in[3];
    const float* q_scale = (const float*)d_in[4];
    const float* k_scale = (const float*)d_in[5];
    const float* w_out   = (const float*)d_in[6];
    const float* s_gamma = (const float*)d_in[7];
    const float* w_q2s   = (const float*)d_in[8];
    const float* w_qfs   = (const float*)d_in[9];
    const float* w_sqkv  = (const float*)d_in[10];
    const float* init_st = (const float*)d_in[11];
    const float* pos_ids = (const float*)d_in[12];
    const float* w_sout  = (const float*)d_in[13];
    const float* ts_q    = (const float*)d_in[14];
    const float* ts_k    = (const float*)d_in[15];
    const float* ss_q    = (const float*)d_in[16];
    const float* ss_k    = (const float*)d_in[17];
    const float* fs_q    = (const float*)d_in[18];
    const float* fs_k    = (const float*)d_in[19];
    const float* w_gate  = (const float*)d_in[20];
    const float* b_gate  = (const float*)d_in[21];
    const float* beta    = (const float*)d_in[22];
    float* out = (float*)d_out;

    float* xn   = symaddr(g_xn);
    float* qkv  = symaddr(g_qkv);
    float* q2s  = symaddr(g_q2s);
    float* sqkv = symaddr(g_state_qkv);
    float* st   = symaddr(g_st);
    float* qfsr = symaddr(g_qfs_raw);
    float* qnm  = symaddr(g_qn_main);
    float* knm  = symaddr(g_kn_main);
    float* qnts = symaddr(g_qn_ts);
    float* knts = symaddr(g_kn_ts);
    float* qnss = symaddr(g_qn_ss);
    float* knss = symaddr(g_kn_ss);
    float* qnfs = symaddr(g_qn_fs);
    float* knfs = symaddr(g_kn_fs);
    float* cat  = symaddr(g_cat);
    float* scat = symaddr(g_state_cat);
    float* so   = symaddr(g_so);
    float* zb   = symaddr(g_z);

    cudaFuncSetAttribute(flashmma, cudaFuncAttributeMaxDynamicSharedMemorySize, FLASH_SMEM);
    cudaFuncSetAttribute(tgemm, cudaFuncAttributeMaxDynamicSharedMemorySize, TGEMM_SMEM);

    // 1) layernorms
    ln_kernel<<<NSEQ, 256>>>(x, gamma, nullptr, xn);
    ln_kernel<<<NST, 256>>>(init_st, s_gamma, pos_ids, st);

    // 2) projections
    tgemm<<<dim3(3072/128, NSEQ/128), 256, TGEMM_SMEM>>>(xn, w_qkv, qkv, NSEQ, 3072, DIMM, 0);
    tgemm<<<dim3(DIMM/128, NSEQ/128), 256, TGEMM_SMEM>>>(xn, w_q2s, q2s, NSEQ, DIMM, DIMM, 0);
    tgemm<<<dim3(3072/128, NST/128), 256, TGEMM_SMEM>>>(init_st, w_sqkv, sqkv, NST, 3072, DIMM, 0);
    tgemm<<<dim3(DIMM/128, NST/128), 256, TGEMM_SMEM>>>(st, w_qfs, qfsr, NST, DIMM, DIMM, 0);

    // 3) l2norm + scale, head-major
    norm_heads<<<dim3(NSEQ, HEADS), 64>>>(qkv, 3072, 0,    0,    q_scale, qnm,  NSEQ);
    norm_heads<<<dim3(NSEQ, HEADS), 64>>>(qkv, 3072, 1024, 0,    k_scale, knm,  NSEQ);
    norm_heads<<<dim3(NSEQ, HEADS), 64>>>(q2s, 1024, 0,    0,    ts_q,    qnts, NSEQ);
    norm_heads<<<dim3(NST,  HEADS), 64>>>(sqkv, 3072, 1024, 0,   ts_k,    knts, NST);
    norm_heads<<<dim3(NST,  HEADS), 64>>>(sqkv, 3072, 0,    0,   ss_q,    qnss, NST);
    norm_heads<<<dim3(NST,  HEADS), 64>>>(sqkv, 3072, 1024, 0,   ss_k,    knss, NST);
    norm_heads<<<dim3(NST,  HEADS), 64>>>(qfsr, 1024, 0,    0,   fs_q,    qnfs, NST);
    norm_heads<<<dim3(NST,  HEADS), 64>>>(qkv,  3072, 1024, 3584, fs_k,   knfs, NST);

    // 4) fused attentions
    flashmma<<<dim3(WIDTH/64, HEADS*NW), 256, FLASH_SMEM>>>(
        qnm, NSEQ, knm, NSEQ, qkv, 3072, HD, 2048, 0, bias,
        cat, 2*DIMM, HD, 0, KEYW, NW);
    flashmma<<<dim3(NSEQ/64, HEADS), 256, FLASH_SMEM>>>(
        qnts, NSEQ, knts, NST, sqkv, 3072, HD, 2048, 0, nullptr,
        cat, 2*DIMM, HD, DIMM, NST, 1);
    flashmma<<<dim3(NST/64, HEADS), 256, FLASH_SMEM>>>(
        qnss, NST, knss, NST, sqkv, 3072, HD, 2048, 0, nullptr,
        scat, 2*DIMM, 2*HD, 0, NST, 1);
    flashmma<<<dim3(NST/64, HEADS), 256, FLASH_SMEM>>>(
        qnfs, NST, knfs, NST, qkv, 3072, HD, 2048, 3584, nullptr,
        scat, 2*DIMM, 2*HD, HD, NST, 1);

    // 5) output projection: out = cat @ w_out (single K=2048 GEMM)
    tgemm<<<dim3(DIMM/128, NSEQ/128), 256, TGEMM_SMEM>>>(cat, w_out, out, NSEQ, DIMM, 2*DIMM, 0);

    // 6) memories
    memories_kernel<<<(2*HEADS*WIDTH*HD)/256, 256>>>(qkv, out + (long)NSEQ*DIMM);

    // 7) state output path
    tgemm<<<dim3(DIMM/128, NST/128), 256, TGEMM_SMEM>>>(scat, w_sout, so, NST, DIMM, 2*DIMM, 0);
    tgemm<<<dim3(DIMM/128, NST/128), 256, TGEMM_SMEM>>>(so, w_gate, zb, NST, DIMM, DIMM, 0);
    newstates_kernel<<<(NST*DIMM)/256, 256>>>(zb, b_gate, beta, init_st,
            out + (long)NSEQ*DIMM + 2*HEADS*WIDTH*HD);
}